// round 12
// baseline (speedup 1.0000x reference)
#include <cuda_runtime.h>
#include <cuda_bf16.h>
#include <math.h>

// ---------------- problem dims ----------------
#define CDIM 512
#define INDIM 256
#define NHEAD 4
#define DHEAD 128
#define FANOUT 16
#define NCLS 47
#define N0 256
#define N1 4096
#define N2 65536
#define NL 2

typedef __nv_bfloat16 bf16;

// ---------------- fp32 scratch ----------------
__device__ float g_s0a[N0 * CDIM];
__device__ float g_s0b[N0 * CDIM];
__device__ float g_s1a[N1 * CDIM];
__device__ float g_s1b[N1 * CDIM];
__device__ float g_s2[(long long)N2 * CDIM];
__device__ float g_hlocal[N1 * CDIM];
__device__ float g_h1[N1 * CDIM];
__device__ float g_h2[N1 * CDIM];

// ---------------- split-bf16 scratch (hi/lo) ----------------
__device__ bf16 g_f2h[(long long)N2 * INDIM], g_f2l[(long long)N2 * INDIM];
__device__ bf16 g_f1h[N1 * INDIM], g_f1l[N1 * INDIM];
__device__ bf16 g_f0h[N0 * INDIM], g_f0l[N0 * INDIM];
__device__ bf16 g_wembh[CDIM * INDIM], g_wembl[CDIM * INDIM];
__device__ bf16 g_wsageh[NL * CDIM * 2 * CDIM], g_wsagel[NL * CDIM * 2 * CDIM];
__device__ bf16 g_wqkvh[NL * 3 * CDIM * CDIM], g_wqkvl[NL * 3 * CDIM * CDIM];
__device__ bf16 g_wouth[NL * CDIM * CDIM], g_woutl[NL * CDIM * CDIM];
__device__ bf16 g_wf1h[NL * 2 * CDIM * CDIM], g_wf1l[NL * 2 * CDIM * CDIM];
__device__ bf16 g_wf2h[NL * CDIM * 2 * CDIM], g_wf2l[NL * CDIM * 2 * CDIM];
__device__ bf16 g_wclsh[NCLS * CDIM + 64], g_wclsl[NCLS * CDIM + 64];
__device__ bf16 g_cch[N1 * 2 * CDIM], g_ccl[N1 * 2 * CDIM];
__device__ bf16 g_h1h[N1 * CDIM], g_h1l[N1 * CDIM];
__device__ bf16 g_h2h[N1 * CDIM], g_h2l[N1 * CDIM];
__device__ bf16 g_qkvh[N1 * 3 * CDIM], g_qkvl[N1 * 3 * CDIM];
__device__ bf16 g_sch[(long long)NHEAD * N1 * N1], g_scl[(long long)NHEAD * N1 * N1];
__device__ bf16 g_vth[NHEAD * DHEAD * N1], g_vtl[NHEAD * DHEAD * N1];
__device__ bf16 g_aoh[N1 * CDIM], g_aol[N1 * CDIM];
__device__ bf16 g_fmh[N1 * 2 * CDIM], g_fml[N1 * 2 * CDIM];
__device__ bf16 g_s0h[N0 * CDIM], g_s0l[N0 * CDIM];

// =====================================================================
// split helpers
// =====================================================================
__device__ __forceinline__ void split1(float x, bf16& h, bf16& l)
{
    h = __float2bfloat16(x);
    l = __float2bfloat16(x - __bfloat162float(h));
}

__global__ void split_kernel(const float* __restrict__ src,
                             bf16* __restrict__ h, bf16* __restrict__ l, long long n4)
{
    for (long long i = blockIdx.x * (long long)blockDim.x + threadIdx.x;
         i < n4; i += (long long)gridDim.x * blockDim.x) {
        float4 v = reinterpret_cast<const float4*>(src)[i];
        union { bf16 b[4]; uint2 u; } uh, ul;
        split1(v.x, uh.b[0], ul.b[0]);
        split1(v.y, uh.b[1], ul.b[1]);
        split1(v.z, uh.b[2], ul.b[2]);
        split1(v.w, uh.b[3], ul.b[3]);
        reinterpret_cast<uint2*>(h)[i] = uh.u;
        reinterpret_cast<uint2*>(l)[i] = ul.u;
    }
}

// =====================================================================
// Tensor-core GEMM (mma.sync bf16, 3-pass split), TRANSB layout:
//   Y = op( A[M,K] * B[N,K]^T )
// Block 128x128x32, 256 thr, 8 warps (4m x 2n), warp tile 32x64.
// cp.async 3-stage pipeline, 120 KB dynamic smem.
// MODE: 0 +bias | 1 (+bias)*rowmask | 2 *alpha | 3 relu(+bias)
//       4 (res + v + bias)*rowmask
// SPLIT_OUT: write (Yh, Yl) bf16 instead of fp32 Y.
// =====================================================================
__device__ __forceinline__ void mma16816(float* c, const unsigned* a, const unsigned* b)
{
    asm volatile(
        "mma.sync.aligned.m16n8k16.row.col.f32.bf16.bf16.f32 "
        "{%0,%1,%2,%3}, {%4,%5,%6,%7}, {%8,%9}, {%0,%1,%2,%3};\n"
        : "+f"(c[0]), "+f"(c[1]), "+f"(c[2]), "+f"(c[3])
        : "r"(a[0]), "r"(a[1]), "r"(a[2]), "r"(a[3]), "r"(b[0]), "r"(b[1]));
}

__device__ __forceinline__ void cp16(unsigned s, const void* g, bool v)
{
    asm volatile("cp.async.cg.shared.global [%0], [%1], 16, %2;\n"
                 :: "r"(s), "l"(g), "r"(v ? 16 : 0));
}
__device__ __forceinline__ void cp_commit()
{
    asm volatile("cp.async.commit_group;\n" ::);
}

#define GEMM_STAGES 3
#define GEMM_SMEM_BYTES (GEMM_STAGES * 4 * 128 * 40 * 2)   // 122880

template <int MODE, bool SPLIT_OUT>
__global__ void __launch_bounds__(256) mma_gemm_kernel(
    const bf16* __restrict__ Ahg, const bf16* __restrict__ Alg,
    const bf16* __restrict__ Bhg, const bf16* __restrict__ Blg,
    const float* __restrict__ bias, const float* __restrict__ res,
    const float* __restrict__ rowmask,
    float* __restrict__ Yg, bf16* __restrict__ Yhg, bf16* __restrict__ Ylg,
    int M, int N, int K, int ldx, int ldw, int ldy,
    long long sX, long long sW, long long sY, float alpha)
{
    constexpr int BM = 128, BN = 128, BK = 32;
    constexpr int LDA = 40;
    constexpr int SZ  = BM * LDA;          // elems per stage per tensor

    extern __shared__ __align__(16) char smem_raw[];
    bf16* sA_h = reinterpret_cast<bf16*>(smem_raw);       // [STAGES][SZ]
    bf16* sA_l = sA_h + GEMM_STAGES * SZ;
    bf16* sB_h = sA_l + GEMM_STAGES * SZ;
    bf16* sB_l = sB_h + GEMM_STAGES * SZ;
    const unsigned sbase = (unsigned)__cvta_generic_to_shared(smem_raw);
    const unsigned offAh = 0;
    const unsigned offAl = GEMM_STAGES * SZ * 2;
    const unsigned offBh = 2 * GEMM_STAGES * SZ * 2;
    const unsigned offBl = 3 * GEMM_STAGES * SZ * 2;

    const bf16* Ah = Ahg + (long long)blockIdx.z * sX;
    const bf16* Al = Alg + (long long)blockIdx.z * sX;
    const bf16* Bh = Bhg + (long long)blockIdx.z * sW;
    const bf16* Bl = Blg + (long long)blockIdx.z * sW;
    float* Y  = Yg  ? Yg  + (long long)blockIdx.z * sY : nullptr;
    bf16*  Yh = Yhg ? Yhg + (long long)blockIdx.z * sY : nullptr;
    bf16*  Yl = Ylg ? Ylg + (long long)blockIdx.z * sY : nullptr;

    const int tid  = threadIdx.x;
    const int warp = tid >> 5;
    const int lane = tid & 31;
    const int wm   = warp & 3;          // 4 m-tiles of 32
    const int wn   = warp >> 2;         // 2 n-tiles of 64
    const int m0   = blockIdx.x * BM;
    const int n0   = blockIdx.y * BN;
    const int r    = lane >> 2;
    const int c2   = (lane & 3) * 2;

    const int lrow = tid >> 2;          // 0..63 (+64 on second pass)
    const int lq   = (tid & 3) * 8;     // 0,8,16,24

    float acc[2][8][4];
#pragma unroll
    for (int mt = 0; mt < 2; mt++)
#pragma unroll
        for (int nt = 0; nt < 8; nt++)
#pragma unroll
            for (int e = 0; e < 4; e++) acc[mt][nt][e] = 0.f;

    const int nk = K / BK;

    auto cp_stage = [&](int buf, int kt) {
        const int k0 = kt * BK;
#pragma unroll
        for (int it = 0; it < 2; it++) {
            const int row = lrow + it * 64;
            const unsigned soff = (unsigned)((buf * SZ + row * LDA + lq) * 2);
            const bool va = (m0 + row) < M;
            const long long ga = (long long)(m0 + row) * ldx + k0 + lq;
            cp16(sbase + offAh + soff, va ? (const void*)(Ah + ga) : (const void*)Ah, va);
            cp16(sbase + offAl + soff, va ? (const void*)(Al + ga) : (const void*)Al, va);
            const bool vb = (n0 + row) < N;
            const long long gb = (long long)(n0 + row) * ldw + k0 + lq;
            cp16(sbase + offBh + soff, vb ? (const void*)(Bh + gb) : (const void*)Bh, vb);
            cp16(sbase + offBl + soff, vb ? (const void*)(Bl + gb) : (const void*)Bl, vb);
        }
        cp_commit();
    };

    cp_stage(0, 0);
    if (nk > 1) cp_stage(1, 1);

    for (int t = 0; t < nk; t++) {
        const int buf = t % GEMM_STAGES;
        if (t + 2 < nk) cp_stage((t + 2) % GEMM_STAGES, t + 2);
        const int pending = (nk - 1 - t) < 2 ? (nk - 1 - t) : 2;
        if (pending == 2)      asm volatile("cp.async.wait_group 2;\n" ::);
        else if (pending == 1) asm volatile("cp.async.wait_group 1;\n" ::);
        else                   asm volatile("cp.async.wait_group 0;\n" ::);
        __syncthreads();

        const bf16* cAh = sA_h + buf * SZ;
        const bf16* cAl = sA_l + buf * SZ;
        const bf16* cBh = sB_h + buf * SZ;
        const bf16* cBl = sB_l + buf * SZ;

#pragma unroll
        for (int ks = 0; ks < 2; ks++) {
            const int koff = ks * 16;
            unsigned ah[2][4], al[2][4], bh[8][2], bl[8][2];
#pragma unroll
            for (int mt = 0; mt < 2; mt++) {
                const int rb = (wm * 32 + mt * 16 + r) * LDA + koff + c2;
                ah[mt][0] = *reinterpret_cast<const unsigned*>(&cAh[rb]);
                ah[mt][1] = *reinterpret_cast<const unsigned*>(&cAh[rb + 8 * LDA]);
                ah[mt][2] = *reinterpret_cast<const unsigned*>(&cAh[rb + 8]);
                ah[mt][3] = *reinterpret_cast<const unsigned*>(&cAh[rb + 8 * LDA + 8]);
                al[mt][0] = *reinterpret_cast<const unsigned*>(&cAl[rb]);
                al[mt][1] = *reinterpret_cast<const unsigned*>(&cAl[rb + 8 * LDA]);
                al[mt][2] = *reinterpret_cast<const unsigned*>(&cAl[rb + 8]);
                al[mt][3] = *reinterpret_cast<const unsigned*>(&cAl[rb + 8 * LDA + 8]);
            }
#pragma unroll
            for (int nt = 0; nt < 8; nt++) {
                const int cb = (wn * 64 + nt * 8 + r) * LDA + koff + c2;
                bh[nt][0] = *reinterpret_cast<const unsigned*>(&cBh[cb]);
                bh[nt][1] = *reinterpret_cast<const unsigned*>(&cBh[cb + 8]);
                bl[nt][0] = *reinterpret_cast<const unsigned*>(&cBl[cb]);
                bl[nt][1] = *reinterpret_cast<const unsigned*>(&cBl[cb + 8]);
            }
#pragma unroll
            for (int mt = 0; mt < 2; mt++)
#pragma unroll
                for (int nt = 0; nt < 8; nt++) {
                    mma16816(acc[mt][nt], ah[mt], bh[nt]);
                    mma16816(acc[mt][nt], ah[mt], bl[nt]);
                    mma16816(acc[mt][nt], al[mt], bh[nt]);
                }
        }
        __syncthreads();
    }

    // ---- epilogue ----
#pragma unroll
    for (int mt = 0; mt < 2; mt++) {
#pragma unroll
        for (int nt = 0; nt < 8; nt++) {
#pragma unroll
            for (int e = 0; e < 4; e++) {
                const int gr = m0 + wm * 32 + mt * 16 + r + (e >= 2 ? 8 : 0);
                const int gc = n0 + wn * 64 + nt * 8 + c2 + (e & 1);
                if (gr >= M || gc >= N) continue;
                float v = acc[mt][nt][e];
                if (MODE == 0)      v = v + bias[gc];
                else if (MODE == 1) v = (v + bias[gc]) * rowmask[gr];
                else if (MODE == 2) v = v * alpha;
                else if (MODE == 3) v = fmaxf(v + bias[gc], 0.f);
                else if (MODE == 4) v = (res[(long long)gr * ldy + gc] + v + bias[gc]) * rowmask[gr];
                const long long off = (long long)gr * ldy + gc;
                if (SPLIT_OUT) {
                    bf16 h, l; split1(v, h, l);
                    Yh[off] = h; Yl[off] = l;
                } else {
                    Y[off] = v;
                }
            }
        }
    }
}

// =====================================================================
// V transpose: qkv[tok][2C + h*DH + d] -> Vt[h][d][tok]  (split bf16)
// =====================================================================
__global__ void __launch_bounds__(256) transpose_v_kernel(
    const bf16* __restrict__ qh, const bf16* __restrict__ ql,
    bf16* __restrict__ vh, bf16* __restrict__ vl, int n)
{
    __shared__ bf16 th[32][34], tl[32][34];
    const int hh = blockIdx.z;
    const int tok0 = blockIdx.x * 32, d0 = blockIdx.y * 32;
    const int tx = threadIdx.x, ty = threadIdx.y;
#pragma unroll
    for (int rr = ty; rr < 32; rr += 8) {
        const long long src = (long long)(tok0 + rr) * (3 * CDIM) + 2 * CDIM + hh * DHEAD + d0 + tx;
        th[rr][tx] = qh[src];
        tl[rr][tx] = ql[src];
    }
    __syncthreads();
#pragma unroll
    for (int rr = ty; rr < 32; rr += 8) {
        const long long dst = ((long long)hh * DHEAD + d0 + rr) * n + tok0 + tx;
        vh[dst] = th[tx][rr];
        vl[dst] = tl[tx][rr];
    }
}

// =====================================================================
// Masked-mean aggregation + concat -> split-bf16 cc
// =====================================================================
__global__ void __launch_bounds__(128) agg_concat_kernel(
    bf16* __restrict__ outh, bf16* __restrict__ outl,
    const float* __restrict__ sf, const float* __restrict__ child,
    const int* __restrict__ nbm)
{
    const int i = blockIdx.x;
    const int tid = threadIdx.x;
    __shared__ float mk[FANOUT];
    __shared__ float invd;
    if (tid < FANOUT) mk[tid] = (float)nbm[i * FANOUT + tid];
    __syncthreads();
    if (tid == 0) {
        float s = 0.f;
#pragma unroll
        for (int f = 0; f < FANOUT; f++) s += mk[f];
        invd = 1.f / fmaxf(s, 1.f);
    }
    __syncthreads();
    const float dinv = invd;
    const long long ob = (long long)i * (2 * CDIM) + tid * 4;

    float4 v0 = *reinterpret_cast<const float4*>(sf + (long long)i * CDIM + tid * 4);
    union { bf16 b[4]; uint2 u; } uh, ul;
    split1(v0.x, uh.b[0], ul.b[0]); split1(v0.y, uh.b[1], ul.b[1]);
    split1(v0.z, uh.b[2], ul.b[2]); split1(v0.w, uh.b[3], ul.b[3]);
    *reinterpret_cast<uint2*>(outh + ob) = uh.u;
    *reinterpret_cast<uint2*>(outl + ob) = ul.u;

    float4 acc = make_float4(0.f, 0.f, 0.f, 0.f);
    const float* cb = child + (long long)i * FANOUT * CDIM + tid * 4;
#pragma unroll
    for (int f = 0; f < FANOUT; f++) {
        float4 v = *reinterpret_cast<const float4*>(cb + f * CDIM);
        float w = mk[f];
        acc.x += v.x * w; acc.y += v.y * w; acc.z += v.z * w; acc.w += v.w * w;
    }
    acc.x *= dinv; acc.y *= dinv; acc.z *= dinv; acc.w *= dinv;
    split1(acc.x, uh.b[0], ul.b[0]); split1(acc.y, uh.b[1], ul.b[1]);
    split1(acc.z, uh.b[2], ul.b[2]); split1(acc.w, uh.b[3], ul.b[3]);
    *reinterpret_cast<uint2*>(outh + ob + CDIM) = uh.u;
    *reinterpret_cast<uint2*>(outl + ob + CDIM) = ul.u;
}

// =====================================================================
// Residual + LayerNorm: fp32 out + fused split-bf16 out
// =====================================================================
__global__ void __launch_bounds__(128) ln_res_kernel(
    float* __restrict__ out, bf16* __restrict__ outh, bf16* __restrict__ outl,
    const float* __restrict__ a, const float* __restrict__ b,
    const float* __restrict__ g, const float* __restrict__ be)
{
    const long long base = (long long)blockIdx.x * CDIM;
    const int tid = threadIdx.x;
    float4 va = *reinterpret_cast<const float4*>(a + base + tid * 4);
    float4 vb = *reinterpret_cast<const float4*>(b + base + tid * 4);
    float x0 = va.x + vb.x, x1 = va.y + vb.y, x2 = va.z + vb.z, x3 = va.w + vb.w;
    float s = x0 + x1 + x2 + x3;
    float q = x0 * x0 + x1 * x1 + x2 * x2 + x3 * x3;
#pragma unroll
    for (int o = 16; o; o >>= 1) {
        s += __shfl_xor_sync(0xffffffffu, s, o);
        q += __shfl_xor_sync(0xffffffffu, q, o);
    }
    __shared__ float shs[4], shq[4];
    if ((tid & 31) == 0) { shs[tid >> 5] = s; shq[tid >> 5] = q; }
    __syncthreads();
    s = shs[0] + shs[1] + shs[2] + shs[3];
    q = shq[0] + shq[1] + shq[2] + shq[3];
    const float mu  = s * (1.f / CDIM);
    const float var = q * (1.f / CDIM) - mu * mu;
    const float rr  = rsqrtf(var + 1e-5f);
    float4 vg  = *reinterpret_cast<const float4*>(g + tid * 4);
    float4 vbe = *reinterpret_cast<const float4*>(be + tid * 4);
    float4 o4;
    o4.x = (x0 - mu) * rr * vg.x + vbe.x;
    o4.y = (x1 - mu) * rr * vg.y + vbe.y;
    o4.z = (x2 - mu) * rr * vg.z + vbe.z;
    o4.w = (x3 - mu) * rr * vg.w + vbe.w;
    *reinterpret_cast<float4*>(out + base + tid * 4) = o4;
    union { bf16 bb[4]; uint2 u; } uh, ul;
    split1(o4.x, uh.bb[0], ul.bb[0]); split1(o4.y, uh.bb[1], ul.bb[1]);
    split1(o4.z, uh.bb[2], ul.bb[2]); split1(o4.w, uh.bb[3], ul.bb[3]);
    *reinterpret_cast<uint2*>(outh + base + tid * 4) = uh.u;
    *reinterpret_cast<uint2*>(outl + base + tid * 4) = ul.u;
}

// =====================================================================
// In-place row softmax on split-bf16 scores (hi+lo reconstructed).
// CNT bf16x2 pairs per thread; NW warps per block.
// =====================================================================
template <int CNT, int NW>
__global__ void __launch_bounds__(NW * 32) softmax_kernel(
    bf16* __restrict__ Sh, bf16* __restrict__ Sl, int n)
{
    const long long rb = ((long long)blockIdx.y * n + blockIdx.x) * n;
    const int tid = threadIdx.x;
    constexpr int NT = NW * 32;

    float2 v[CNT];
#pragma unroll
    for (int t = 0; t < CNT; t++) {
        const long long idx = rb + (long long)(tid + t * NT) * 2;
        unsigned uh = *reinterpret_cast<const unsigned*>(&Sh[idx]);
        unsigned ul = *reinterpret_cast<const unsigned*>(&Sl[idx]);
        __nv_bfloat162 bh = *reinterpret_cast<__nv_bfloat162*>(&uh);
        __nv_bfloat162 bl = *reinterpret_cast<__nv_bfloat162*>(&ul);
        v[t].x = __bfloat162float(bh.x) + __bfloat162float(bl.x);
        v[t].y = __bfloat162float(bh.y) + __bfloat162float(bl.y);
    }

    float m = -1e30f;
#pragma unroll
    for (int t = 0; t < CNT; t++) m = fmaxf(m, fmaxf(v[t].x, v[t].y));
    __shared__ float sh[NW];
#pragma unroll
    for (int o = 16; o; o >>= 1) m = fmaxf(m, __shfl_xor_sync(0xffffffffu, m, o));
    if ((tid & 31) == 0) sh[tid >> 5] = m;
    __syncthreads();
    float mm = sh[0];
#pragma unroll
    for (int w = 1; w < NW; w++) mm = fmaxf(mm, sh[w]);

    float s = 0.f;
#pragma unroll
    for (int t = 0; t < CNT; t++) {
        v[t].x = expf(v[t].x - mm);
        v[t].y = expf(v[t].y - mm);
        s += v[t].x + v[t].y;
    }
    __syncthreads();
#pragma unroll
    for (int o = 16; o; o >>= 1) s += __shfl_xor_sync(0xffffffffu, s, o);
    if ((tid & 31) == 0) sh[tid >> 5] = s;
    __syncthreads();
    float tot = 0.f;
#pragma unroll
    for (int w = 0; w < NW; w++) tot += sh[w];
    const float inv = 1.f / tot;

#pragma unroll
    for (int t = 0; t < CNT; t++) {
        const long long idx = rb + (long long)(tid + t * NT) * 2;
        union { bf16 b[2]; unsigned u; } ph, pl;
        split1(v[t].x * inv, ph.b[0], pl.b[0]);
        split1(v[t].y * inv, ph.b[1], pl.b[1]);
        *reinterpret_cast<unsigned*>(&Sh[idx]) = ph.u;
        *reinterpret_cast<unsigned*>(&Sl[idx]) = pl.u;
    }
}

// =====================================================================
// Host-side helpers
// =====================================================================
template <int MODE, bool SO>
static inline void launch_mma(const bf16* Ah, const bf16* Al,
                              const bf16* Bh, const bf16* Bl,
                              const float* bias, const float* res, const float* rm,
                              float* Y, bf16* Yh, bf16* Yl,
                              int M, int N, int K, int ldx, int ldw, int ldy,
                              long long sX = 0, long long sW = 0, long long sY = 0,
                              int batch = 1, float alpha = 1.f)
{
    dim3 grid((M + 127) / 128, (N + 127) / 128, batch);
    mma_gemm_kernel<MODE, SO><<<grid, 256, GEMM_SMEM_BYTES>>>(
        Ah, Al, Bh, Bl, bias, res, rm, Y, Yh, Yl,
        M, N, K, ldx, ldw, ldy, sX, sW, sY, alpha);
}

static inline void launch_split(const float* s, bf16* h, bf16* l, long long cnt)
{
    long long n4 = cnt / 4;
    int grid = (int)((n4 + 255) / 256);
    if (grid > 4096) grid = 4096;
    split_kernel<<<grid, 256>>>(s, h, l, n4);
}

// Cached scratch pointers
static float *s0a, *s0b, *s1a, *s1b, *s2, *hl, *h1, *h2p;
static bf16 *f2h, *f2l, *f1h, *f1l, *f0h, *f0l;
static bf16 *wembh, *wembl, *wsageh, *wsagel, *wqkvh, *wqkvl, *wouth, *woutl;
static bf16 *wf1h, *wf1l, *wf2h, *wf2l, *wclsh, *wclsl;
static bf16 *cch, *ccl, *h1h, *h1l, *h2h, *h2l, *qkvh, *qkvl;
static bf16 *sch, *scl, *vth, *vtl, *aoh, *aol, *fmh, *fml, *s0h, *s0l;
static bool g_ptrs_ready = false;

#define SYM(p, s) cudaGetSymbolAddress((void**)&(p), s)
#define SETSMEM(MODE, SO) \
    cudaFuncSetAttribute(mma_gemm_kernel<MODE, SO>, \
        cudaFuncAttributeMaxDynamicSharedMemorySize, GEMM_SMEM_BYTES)

static void resolve_ptrs()
{
    if (g_ptrs_ready) return;
    SYM(s0a, g_s0a); SYM(s0b, g_s0b); SYM(s1a, g_s1a); SYM(s1b, g_s1b);
    SYM(s2, g_s2); SYM(hl, g_hlocal); SYM(h1, g_h1); SYM(h2p, g_h2);
    SYM(f2h, g_f2h); SYM(f2l, g_f2l); SYM(f1h, g_f1h); SYM(f1l, g_f1l);
    SYM(f0h, g_f0h); SYM(f0l, g_f0l);
    SYM(wembh, g_wembh); SYM(wembl, g_wembl);
    SYM(wsageh, g_wsageh); SYM(wsagel, g_wsagel);
    SYM(wqkvh, g_wqkvh); SYM(wqkvl, g_wqkvl);
    SYM(wouth, g_wouth); SYM(woutl, g_woutl);
    SYM(wf1h, g_wf1h); SYM(wf1l, g_wf1l);
    SYM(wf2h, g_wf2h); SYM(wf2l, g_wf2l);
    SYM(wclsh, g_wclsh); SYM(wclsl, g_wclsl);
    SYM(cch, g_cch); SYM(ccl, g_ccl);
    SYM(h1h, g_h1h); SYM(h1l, g_h1l);
    SYM(h2h, g_h2h); SYM(h2l, g_h2l);
    SYM(qkvh, g_qkvh); SYM(qkvl, g_qkvl);
    SYM(sch, g_sch); SYM(scl, g_scl);
    SYM(vth, g_vth); SYM(vtl, g_vtl);
    SYM(aoh, g_aoh); SYM(aol, g_aol);
    SYM(fmh, g_fmh); SYM(fml, g_fml);
    SYM(s0h, g_s0h); SYM(s0l, g_s0l);
    SETSMEM(0, false); SETSMEM(0, true);
    SETSMEM(1, false);
    SETSMEM(2, true);
    SETSMEM(3, true);
    SETSMEM(4, false); SETSMEM(4, true);
    g_ptrs_ready = true;
}

extern "C" void kernel_launch(void* const* d_in, const int* in_sizes, int n_in,
                              void* d_out, int out_size)
{
    (void)in_sizes; (void)n_in; (void)out_size;
    const float* feats0  = (const float*)d_in[0];
    const float* feats1  = (const float*)d_in[1];
    const float* feats2  = (const float*)d_in[2];
    const float* nmask0  = (const float*)d_in[3];
    const float* nmask1  = (const float*)d_in[4];
    const float* nmask2  = (const float*)d_in[5];
    const int*   nbmask0 = (const int*)d_in[6];
    const int*   nbmask1 = (const int*)d_in[7];
    const float* emb_w   = (const float*)d_in[8];
    const float* emb_b   = (const float*)d_in[9];
    const float* sage_w  = (const float*)d_in[10];
    const float* sage_b  = (const float*)d_in[11];
    const float* qkv_w   = (const float*)d_in[12];
    const float* qkv_b   = (const float*)d_in[13];
    const float* out_w   = (const float*)d_in[14];
    const float* out_b   = (const float*)d_in[15];
    const float* n1_g    = (const float*)d_in[16];
    const float* n1_b    = (const float*)d_in[17];
    const float* n2_g    = (const float*)d_in[18];
    const float* n2_b    = (const float*)d_in[19];
    const float* ffn_w1  = (const float*)d_in[20];
    const float* ffn_b1  = (const float*)d_in[21];
    const float* ffn_w2  = (const float*)d_in[22];
    const float* ffn_b2  = (const float*)d_in[23];
    const float* cls_w   = (const float*)d_in[24];
    const float* cls_b   = (const float*)d_in[25];
    float* out = (float*)d_out;

    resolve_ptrs();

    // ---- pre-split inputs & weights (bf16 hi/lo) ----
    launch_split(feats2, f2h, f2l, (long long)N2 * INDIM);
    launch_split(feats1, f1h, f1l, (long long)N1 * INDIM);
    launch_split(feats0, f0h, f0l, (long long)N0 * INDIM);
    launch_split(emb_w,  wembh, wembl, (long long)CDIM * INDIM);
    launch_split(sage_w, wsageh, wsagel, (long long)NL * CDIM * 2 * CDIM);
    launch_split(qkv_w,  wqkvh, wqkvl, (long long)NL * 3 * CDIM * CDIM);
    launch_split(out_w,  wouth, woutl, (long long)NL * CDIM * CDIM);
    launch_split(ffn_w1, wf1h, wf1l, (long long)NL * 2 * CDIM * CDIM);
    launch_split(ffn_w2, wf2h, wf2l, (long long)NL * CDIM * 2 * CDIM);
    launch_split(cls_w,  wclsh, wclsl, (long long)NCLS * CDIM);

    // ---- embeddings ----
    launch_mma<1, false>(f2h, f2l, wembh, wembl, emb_b, nullptr, nmask2,
                         s2, nullptr, nullptr, N2, CDIM, INDIM, INDIM, INDIM, CDIM);
    launch_mma<1, false>(f1h, f1l, wembh, wembl, emb_b, nullptr, nmask1,
                         s1a, nullptr, nullptr, N1, CDIM, INDIM, INDIM, INDIM, CDIM);
    launch_mma<1, false>(f0h, f0l, wembh, wembl, emb_b, nullptr, nmask0,
                         s0a, nullptr, nullptr, N0, CDIM, INDIM, INDIM, INDIM, CDIM);

    struct Step { int li, n; float *sf, *child, *outb; const int* nbm; const float* nm; bool last; };
    Step steps[3] = {
        {0, N1, s1a, s2,  s1b, nbmask1, nmask1, false},
        {0, N0, s0a, s1a, s0b, nbmask0, nmask0, false},
        {1, N0, s0b, s1b, nullptr, nbmask0, nmask0, true},
    };

    const float scale = 1.f / sqrtf((float)DHEAD);

    for (int si = 0; si < 3; si++) {
        const Step& st = steps[si];
        const int li = st.li, n = st.n;
        const bf16* swh = wsageh + (long long)li * CDIM * 2 * CDIM;
        const bf16* swl = wsagel + (long long)li * CDIM * 2 * CDIM;
        const float* sb = sage_b + li * CDIM;
        const bf16* qwh = wqkvh + (long long)li * 3 * CDIM * CDIM;
        const bf16* qwl = wqkvl + (long long)li * 3 * CDIM * CDIM;
        const float* qb = qkv_b + li * 3 * CDIM;
        const bf16* owh = wouth + (long long)li * CDIM * CDIM;
        const bf16* owl = woutl + (long long)li * CDIM * CDIM;
        const float* ob = out_b + li * CDIM;
        const float* g1 = n1_g + li * CDIM, *b1 = n1_b + li * CDIM;
        const float* g2 = n2_g + li * CDIM, *b2 = n2_b + li * CDIM;
        const bf16* f1wh = wf1h + (long long)li * 2 * CDIM * CDIM;
        const bf16* f1wl = wf1l + (long long)li * 2 * CDIM * CDIM;
        const float* fb1 = ffn_b1 + li * 2 * CDIM;
        const bf16* f2wh = wf2h + (long long)li * CDIM * 2 * CDIM;
        const bf16* f2wl = wf2l + (long long)li * CDIM * 2 * CDIM;
        const float* fb2 = ffn_b2 + li * CDIM;

        // 1) aggregate + concat -> split cc
        agg_concat_kernel<<<n, 128>>>(cch, ccl, st.sf, st.child, st.nbm);
        // 2) h_local = cc @ sage_w^T + sage_b
        launch_mma<0, false>(cch, ccl, swh, swl, sb, nullptr, nullptr,
                             hl, nullptr, nullptr,
                             n, CDIM, 2 * CDIM, 2 * CDIM, 2 * CDIM, CDIM);
        // 3) h1 = LN(sf + h_local)
        ln_res_kernel<<<n, 128>>>(h1, h1h, h1l, st.sf, hl, g1, b1);
        // 4) qkv
        launch_mma<0, true>(h1h, h1l, qwh, qwl, qb, nullptr, nullptr,
                            nullptr, qkvh, qkvl,
                            n, 3 * CDIM, CDIM, CDIM, CDIM, 3 * CDIM);
        // 5) scores = scale * Q K^T  (batched heads; split-bf16 out)
        launch_mma<2, true>(qkvh, qkvl, qkvh + CDIM, qkvl + CDIM,
                            nullptr, nullptr, nullptr,
                            nullptr, sch, scl,
                            n, n, DHEAD, 3 * CDIM, 3 * CDIM, n,
                            DHEAD, DHEAD, (long long)n * n, NHEAD, scale);
        // 6) softmax in-place on split scores
        if (n == N1) softmax_kernel<8, 8><<<dim3(N1, NHEAD), 256>>>(sch, scl, n);
        else         softmax_kernel<1, 4><<<dim3(N0, NHEAD), 128>>>(sch, scl, n);
        // 6b) transpose V -> Vt[h][d][tok]
        transpose_v_kernel<<<dim3(n / 32, DHEAD / 32, NHEAD), dim3(32, 8)>>>(
            qkvh, qkvl, vth, vtl, n);
        // 7) O_h = P_h @ V_h^T
        launch_mma<2, true>(sch, scl, vth, vtl,
                            nullptr, nullptr, nullptr,
                            nullptr, aoh, aol,
                            n, DHEAD, n, n, n, CDIM,
                            (long long)n * n, (long long)DHEAD * n, DHEAD, NHEAD, 1.f);
        // 8) proj
        launch_mma<0, false>(aoh, aol, owh, owl, ob, nullptr, nullptr,
                             hl, nullptr, nullptr,
                             n, CDIM, CDIM, CDIM, CDIM, CDIM);
        // 9) h2 = LN(h1 + proj)
        ln_res_kernel<<<n, 128>>>(h2p, h2h, h2l, h1, hl, g2, b2);
        // 10) mid = relu(...)
        launch_mma<3, true>(h2h, h2l, f1wh, f1wl, fb1, nullptr, nullptr,
                            nullptr, fmh, fml,
                            n, 2 * CDIM, CDIM, CDIM, CDIM, 2 * CDIM);
        // 11) state
        if (st.last)
            launch_mma<4, true>(fmh, fml, f2wh, f2wl, fb2, h2p, st.nm,
                                nullptr, s0h, s0l,
                                n, CDIM, 2 * CDIM, 2 * CDIM, 2 * CDIM, CDIM);
        else
            launch_mma<4, false>(fmh, fml, f2wh, f2wl, fb2, h2p, st.nm,
                                 st.outb, nullptr, nullptr,
                                 n, CDIM, 2 * CDIM, 2 * CDIM, 2 * CDIM, CDIM);
    }

    // ---- classifier ----
    launch_mma<0, false>(s0h, s0l, wclsh, wclsl, cls_b, nullptr, nullptr,
                         out, nullptr, nullptr,
                         N0, NCLS, CDIM, CDIM, CDIM, NCLS);
}

// round 13
// speedup vs baseline: 1.0213x; 1.0213x over previous
#include <cuda_runtime.h>
#include <cuda_bf16.h>
#include <math.h>

// ---------------- problem dims ----------------
#define CDIM 512
#define INDIM 256
#define NHEAD 4
#define DHEAD 128
#define FANOUT 16
#define NCLS 47
#define N0 256
#define N1 4096
#define N2 65536
#define NL 2

typedef __nv_bfloat16 bf16;

// ---------------- fp32 scratch ----------------
__device__ float g_s0a[N0 * CDIM];
__device__ float g_s0b[N0 * CDIM];
__device__ float g_s1a[N1 * CDIM];
__device__ float g_s1b[N1 * CDIM];
__device__ float g_s2[(long long)N2 * CDIM];
__device__ float g_hlocal[N1 * CDIM];
__device__ float g_h1[N1 * CDIM];
__device__ float g_h2[N1 * CDIM];

// ---------------- split-bf16 scratch (hi/lo) ----------------
__device__ bf16 g_f2h[(long long)N2 * INDIM], g_f2l[(long long)N2 * INDIM];
__device__ bf16 g_f1h[N1 * INDIM], g_f1l[N1 * INDIM];
__device__ bf16 g_f0h[N0 * INDIM], g_f0l[N0 * INDIM];
__device__ bf16 g_wembh[CDIM * INDIM], g_wembl[CDIM * INDIM];
__device__ bf16 g_wsageh[NL * CDIM * 2 * CDIM], g_wsagel[NL * CDIM * 2 * CDIM];
__device__ bf16 g_wqkvh[NL * 3 * CDIM * CDIM], g_wqkvl[NL * 3 * CDIM * CDIM];
__device__ bf16 g_wouth[NL * CDIM * CDIM], g_woutl[NL * CDIM * CDIM];
__device__ bf16 g_wf1h[NL * 2 * CDIM * CDIM], g_wf1l[NL * 2 * CDIM * CDIM];
__device__ bf16 g_wf2h[NL * CDIM * 2 * CDIM], g_wf2l[NL * CDIM * 2 * CDIM];
__device__ bf16 g_wclsh[NCLS * CDIM + 64], g_wclsl[NCLS * CDIM + 64];
__device__ bf16 g_cch[N1 * 2 * CDIM], g_ccl[N1 * 2 * CDIM];
__device__ bf16 g_h1h[N1 * CDIM], g_h1l[N1 * CDIM];
__device__ bf16 g_h2h[N1 * CDIM], g_h2l[N1 * CDIM];
__device__ bf16 g_qkvh[N1 * 3 * CDIM], g_qkvl[N1 * 3 * CDIM];
__device__ bf16 g_sch[(long long)NHEAD * N1 * N1], g_scl[(long long)NHEAD * N1 * N1];
__device__ bf16 g_vth[NHEAD * DHEAD * N1], g_vtl[NHEAD * DHEAD * N1];
__device__ bf16 g_aoh[N1 * CDIM], g_aol[N1 * CDIM];
__device__ bf16 g_fmh[N1 * 2 * CDIM], g_fml[N1 * 2 * CDIM];
__device__ bf16 g_s0h[N0 * CDIM], g_s0l[N0 * CDIM];

// =====================================================================
// split helpers
// =====================================================================
__device__ __forceinline__ void split1(float x, bf16& h, bf16& l)
{
    h = __float2bfloat16(x);
    l = __float2bfloat16(x - __bfloat162float(h));
}

__global__ void split_kernel(const float* __restrict__ src,
                             bf16* __restrict__ h, bf16* __restrict__ l, long long n4)
{
    for (long long i = blockIdx.x * (long long)blockDim.x + threadIdx.x;
         i < n4; i += (long long)gridDim.x * blockDim.x) {
        float4 v = reinterpret_cast<const float4*>(src)[i];
        union { bf16 b[4]; uint2 u; } uh, ul;
        split1(v.x, uh.b[0], ul.b[0]);
        split1(v.y, uh.b[1], ul.b[1]);
        split1(v.z, uh.b[2], ul.b[2]);
        split1(v.w, uh.b[3], ul.b[3]);
        reinterpret_cast<uint2*>(h)[i] = uh.u;
        reinterpret_cast<uint2*>(l)[i] = ul.u;
    }
}

// =====================================================================
// Tensor-core GEMM (mma.sync bf16, 3-pass split), TRANSB layout:
//   Y = op( A[M,K] * B[N,K]^T )
// Block 128x128x32, 256 thr, 8 warps (4m x 2n), warp tile 32x64.
// 2-stage cp.async (80 KB smem -> 2 CTAs/SM); fragments via ldmatrix.x4.
// MODE: 0 +bias | 1 (+bias)*rowmask | 2 *alpha | 3 relu(+bias)
//       4 (res + v + bias)*rowmask
// SPLIT_OUT: write (Yh, Yl) bf16 instead of fp32 Y.
// =====================================================================
__device__ __forceinline__ void mma16816(float* c, const unsigned* a, const unsigned* b)
{
    asm volatile(
        "mma.sync.aligned.m16n8k16.row.col.f32.bf16.bf16.f32 "
        "{%0,%1,%2,%3}, {%4,%5,%6,%7}, {%8,%9}, {%0,%1,%2,%3};\n"
        : "+f"(c[0]), "+f"(c[1]), "+f"(c[2]), "+f"(c[3])
        : "r"(a[0]), "r"(a[1]), "r"(a[2]), "r"(a[3]), "r"(b[0]), "r"(b[1]));
}

__device__ __forceinline__ void ldsm4(unsigned* d, unsigned saddr)
{
    asm volatile(
        "ldmatrix.sync.aligned.m8n8.x4.shared.b16 {%0,%1,%2,%3}, [%4];\n"
        : "=r"(d[0]), "=r"(d[1]), "=r"(d[2]), "=r"(d[3]) : "r"(saddr));
}

__device__ __forceinline__ void cp16(unsigned s, const void* g, bool v)
{
    asm volatile("cp.async.cg.shared.global [%0], [%1], 16, %2;\n"
                 :: "r"(s), "l"(g), "r"(v ? 16 : 0));
}
__device__ __forceinline__ void cp_commit()
{
    asm volatile("cp.async.commit_group;\n" ::);
}

#define GEMM_SMEM_BYTES (2 * 4 * 128 * 40 * 2)   // 81920 -> 2 CTAs/SM

template <int MODE, bool SPLIT_OUT>
__global__ void __launch_bounds__(256) mma_gemm_kernel(
    const bf16* __restrict__ Ahg, const bf16* __restrict__ Alg,
    const bf16* __restrict__ Bhg, const bf16* __restrict__ Blg,
    const float* __restrict__ bias, const float* __restrict__ res,
    const float* __restrict__ rowmask,
    float* __restrict__ Yg, bf16* __restrict__ Yhg, bf16* __restrict__ Ylg,
    int M, int N, int K, int ldx, int ldw, int ldy,
    long long sX, long long sW, long long sY, float alpha)
{
    constexpr int BM = 128, BN = 128, BK = 32;
    constexpr int LDA = 40;                 // pitch (elems); 80B rows, LDSM-clean
    constexpr int SZ  = BM * LDA;           // elems per stage per tensor

    extern __shared__ __align__(16) char smem_raw[];
    const unsigned sbase = (unsigned)__cvta_generic_to_shared(smem_raw);
    const unsigned offAh = 0;
    const unsigned offAl = 2 * SZ * 2;
    const unsigned offBh = 4 * SZ * 2;
    const unsigned offBl = 6 * SZ * 2;

    const bf16* Ah = Ahg + (long long)blockIdx.z * sX;
    const bf16* Al = Alg + (long long)blockIdx.z * sX;
    const bf16* Bh = Bhg + (long long)blockIdx.z * sW;
    const bf16* Bl = Blg + (long long)blockIdx.z * sW;
    float* Y  = Yg  ? Yg  + (long long)blockIdx.z * sY : nullptr;
    bf16*  Yh = Yhg ? Yhg + (long long)blockIdx.z * sY : nullptr;
    bf16*  Yl = Ylg ? Ylg + (long long)blockIdx.z * sY : nullptr;

    const int tid  = threadIdx.x;
    const int warp = tid >> 5;
    const int lane = tid & 31;
    const int wm   = warp & 3;          // 4 m-tiles of 32
    const int wn   = warp >> 2;         // 2 n-tiles of 64
    const int m0   = blockIdx.x * BM;
    const int n0   = blockIdx.y * BN;
    const int r    = lane >> 2;
    const int c2   = (lane & 3) * 2;

    // LDSM per-lane address pieces: lanes 0-15 -> rows, lanes 16-31 -> k+8
    const int lane15 = lane & 15;
    const int khalf  = (lane >> 4) << 3;          // 0 or 8
    const int aFrag  = (wm * 32 + lane15) * LDA + khalf;   // + mt*16*LDA + koff
    const int bFrag  = (wn * 64 + lane15) * LDA + khalf;   // + j*16*LDA + koff

    const int lrow = tid >> 2;          // cp.async: 0..63 (+64 second pass)
    const int lq   = (tid & 3) * 8;

    float acc[2][8][4];
#pragma unroll
    for (int mt = 0; mt < 2; mt++)
#pragma unroll
        for (int nt = 0; nt < 8; nt++)
#pragma unroll
            for (int e = 0; e < 4; e++) acc[mt][nt][e] = 0.f;

    const int nk = K / BK;

    auto cp_stage = [&](int buf, int kt) {
        const int k0 = kt * BK;
#pragma unroll
        for (int it = 0; it < 2; it++) {
            const int row = lrow + it * 64;
            const unsigned soff = (unsigned)((buf * SZ + row * LDA + lq) * 2);
            const bool va = (m0 + row) < M;
            const long long ga = (long long)(m0 + row) * ldx + k0 + lq;
            cp16(sbase + offAh + soff, va ? (const void*)(Ah + ga) : (const void*)Ah, va);
            cp16(sbase + offAl + soff, va ? (const void*)(Al + ga) : (const void*)Al, va);
            const bool vb = (n0 + row) < N;
            const long long gb = (long long)(n0 + row) * ldw + k0 + lq;
            cp16(sbase + offBh + soff, vb ? (const void*)(Bh + gb) : (const void*)Bh, vb);
            cp16(sbase + offBl + soff, vb ? (const void*)(Bl + gb) : (const void*)Bl, vb);
        }
        cp_commit();
    };

    cp_stage(0, 0);

    for (int t = 0; t < nk; t++) {
        const int buf = t & 1;
        if (t + 1 < nk) {
            cp_stage(buf ^ 1, t + 1);
            asm volatile("cp.async.wait_group 1;\n" ::);
        } else {
            asm volatile("cp.async.wait_group 0;\n" ::);
        }
        __syncthreads();

        const unsigned sb2 = (unsigned)(buf * SZ * 2);

#pragma unroll
        for (int ks = 0; ks < 2; ks++) {
            const int koff = ks * 16;
            unsigned ah[2][4], al[2][4], bh[8][2], bl[8][2];
#pragma unroll
            for (int mt = 0; mt < 2; mt++) {
                const unsigned ao = sb2 + (unsigned)((aFrag + mt * 16 * LDA + koff) * 2);
                ldsm4(ah[mt], sbase + offAh + ao);
                ldsm4(al[mt], sbase + offAl + ao);
            }
#pragma unroll
            for (int j = 0; j < 4; j++) {
                const unsigned bo = sb2 + (unsigned)((bFrag + j * 16 * LDA + koff) * 2);
                unsigned d[4];
                ldsm4(d, sbase + offBh + bo);
                bh[2 * j][0] = d[0]; bh[2 * j + 1][0] = d[1];
                bh[2 * j][1] = d[2]; bh[2 * j + 1][1] = d[3];
                ldsm4(d, sbase + offBl + bo);
                bl[2 * j][0] = d[0]; bl[2 * j + 1][0] = d[1];
                bl[2 * j][1] = d[2]; bl[2 * j + 1][1] = d[3];
            }
#pragma unroll
            for (int mt = 0; mt < 2; mt++)
#pragma unroll
                for (int nt = 0; nt < 8; nt++) {
                    mma16816(acc[mt][nt], ah[mt], bh[nt]);
                    mma16816(acc[mt][nt], ah[mt], bl[nt]);
                    mma16816(acc[mt][nt], al[mt], bh[nt]);
                }
        }
        __syncthreads();
    }

    // ---- epilogue ----
#pragma unroll
    for (int mt = 0; mt < 2; mt++) {
#pragma unroll
        for (int nt = 0; nt < 8; nt++) {
#pragma unroll
            for (int e = 0; e < 4; e++) {
                const int gr = m0 + wm * 32 + mt * 16 + r + (e >= 2 ? 8 : 0);
                const int gc = n0 + wn * 64 + nt * 8 + c2 + (e & 1);
                if (gr >= M || gc >= N) continue;
                float v = acc[mt][nt][e];
                if (MODE == 0)      v = v + bias[gc];
                else if (MODE == 1) v = (v + bias[gc]) * rowmask[gr];
                else if (MODE == 2) v = v * alpha;
                else if (MODE == 3) v = fmaxf(v + bias[gc], 0.f);
                else if (MODE == 4) v = (res[(long long)gr * ldy + gc] + v + bias[gc]) * rowmask[gr];
                const long long off = (long long)gr * ldy + gc;
                if (SPLIT_OUT) {
                    bf16 h, l; split1(v, h, l);
                    Yh[off] = h; Yl[off] = l;
                } else {
                    Y[off] = v;
                }
            }
        }
    }
}

// =====================================================================
// V transpose: qkv[tok][2C + h*DH + d] -> Vt[h][d][tok]  (split bf16)
// =====================================================================
__global__ void __launch_bounds__(256) transpose_v_kernel(
    const bf16* __restrict__ qh, const bf16* __restrict__ ql,
    bf16* __restrict__ vh, bf16* __restrict__ vl, int n)
{
    __shared__ bf16 th[32][34], tl[32][34];
    const int hh = blockIdx.z;
    const int tok0 = blockIdx.x * 32, d0 = blockIdx.y * 32;
    const int tx = threadIdx.x, ty = threadIdx.y;
#pragma unroll
    for (int rr = ty; rr < 32; rr += 8) {
        const long long src = (long long)(tok0 + rr) * (3 * CDIM) + 2 * CDIM + hh * DHEAD + d0 + tx;
        th[rr][tx] = qh[src];
        tl[rr][tx] = ql[src];
    }
    __syncthreads();
#pragma unroll
    for (int rr = ty; rr < 32; rr += 8) {
        const long long dst = ((long long)hh * DHEAD + d0 + rr) * n + tok0 + tx;
        vh[dst] = th[tx][rr];
        vl[dst] = tl[tx][rr];
    }
}

// =====================================================================
// Masked-mean aggregation + concat -> split-bf16 cc
// =====================================================================
__global__ void __launch_bounds__(128) agg_concat_kernel(
    bf16* __restrict__ outh, bf16* __restrict__ outl,
    const float* __restrict__ sf, const float* __restrict__ child,
    const int* __restrict__ nbm)
{
    const int i = blockIdx.x;
    const int tid = threadIdx.x;
    __shared__ float mk[FANOUT];
    __shared__ float invd;
    if (tid < FANOUT) mk[tid] = (float)nbm[i * FANOUT + tid];
    __syncthreads();
    if (tid == 0) {
        float s = 0.f;
#pragma unroll
        for (int f = 0; f < FANOUT; f++) s += mk[f];
        invd = 1.f / fmaxf(s, 1.f);
    }
    __syncthreads();
    const float dinv = invd;
    const long long ob = (long long)i * (2 * CDIM) + tid * 4;

    float4 v0 = *reinterpret_cast<const float4*>(sf + (long long)i * CDIM + tid * 4);
    union { bf16 b[4]; uint2 u; } uh, ul;
    split1(v0.x, uh.b[0], ul.b[0]); split1(v0.y, uh.b[1], ul.b[1]);
    split1(v0.z, uh.b[2], ul.b[2]); split1(v0.w, uh.b[3], ul.b[3]);
    *reinterpret_cast<uint2*>(outh + ob) = uh.u;
    *reinterpret_cast<uint2*>(outl + ob) = ul.u;

    float4 acc = make_float4(0.f, 0.f, 0.f, 0.f);
    const float* cb = child + (long long)i * FANOUT * CDIM + tid * 4;
#pragma unroll
    for (int f = 0; f < FANOUT; f++) {
        float4 v = *reinterpret_cast<const float4*>(cb + f * CDIM);
        float w = mk[f];
        acc.x += v.x * w; acc.y += v.y * w; acc.z += v.z * w; acc.w += v.w * w;
    }
    acc.x *= dinv; acc.y *= dinv; acc.z *= dinv; acc.w *= dinv;
    split1(acc.x, uh.b[0], ul.b[0]); split1(acc.y, uh.b[1], ul.b[1]);
    split1(acc.z, uh.b[2], ul.b[2]); split1(acc.w, uh.b[3], ul.b[3]);
    *reinterpret_cast<uint2*>(outh + ob + CDIM) = uh.u;
    *reinterpret_cast<uint2*>(outl + ob + CDIM) = ul.u;
}

// =====================================================================
// Residual + LayerNorm: fp32 out + fused split-bf16 out
// =====================================================================
__global__ void __launch_bounds__(128) ln_res_kernel(
    float* __restrict__ out, bf16* __restrict__ outh, bf16* __restrict__ outl,
    const float* __restrict__ a, const float* __restrict__ b,
    const float* __restrict__ g, const float* __restrict__ be)
{
    const long long base = (long long)blockIdx.x * CDIM;
    const int tid = threadIdx.x;
    float4 va = *reinterpret_cast<const float4*>(a + base + tid * 4);
    float4 vb = *reinterpret_cast<const float4*>(b + base + tid * 4);
    float x0 = va.x + vb.x, x1 = va.y + vb.y, x2 = va.z + vb.z, x3 = va.w + vb.w;
    float s = x0 + x1 + x2 + x3;
    float q = x0 * x0 + x1 * x1 + x2 * x2 + x3 * x3;
#pragma unroll
    for (int o = 16; o; o >>= 1) {
        s += __shfl_xor_sync(0xffffffffu, s, o);
        q += __shfl_xor_sync(0xffffffffu, q, o);
    }
    __shared__ float shs[4], shq[4];
    if ((tid & 31) == 0) { shs[tid >> 5] = s; shq[tid >> 5] = q; }
    __syncthreads();
    s = shs[0] + shs[1] + shs[2] + shs[3];
    q = shq[0] + shq[1] + shq[2] + shq[3];
    const float mu  = s * (1.f / CDIM);
    const float var = q * (1.f / CDIM) - mu * mu;
    const float rr  = rsqrtf(var + 1e-5f);
    float4 vg  = *reinterpret_cast<const float4*>(g + tid * 4);
    float4 vbe = *reinterpret_cast<const float4*>(be + tid * 4);
    float4 o4;
    o4.x = (x0 - mu) * rr * vg.x + vbe.x;
    o4.y = (x1 - mu) * rr * vg.y + vbe.y;
    o4.z = (x2 - mu) * rr * vg.z + vbe.z;
    o4.w = (x3 - mu) * rr * vg.w + vbe.w;
    *reinterpret_cast<float4*>(out + base + tid * 4) = o4;
    union { bf16 bb[4]; uint2 u; } uh, ul;
    split1(o4.x, uh.bb[0], ul.bb[0]); split1(o4.y, uh.bb[1], ul.bb[1]);
    split1(o4.z, uh.bb[2], ul.bb[2]); split1(o4.w, uh.bb[3], ul.bb[3]);
    *reinterpret_cast<uint2*>(outh + base + tid * 4) = uh.u;
    *reinterpret_cast<uint2*>(outl + base + tid * 4) = ul.u;
}

// =====================================================================
// In-place row softmax on split-bf16 scores (hi+lo reconstructed).
// =====================================================================
template <int CNT, int NW>
__global__ void __launch_bounds__(NW * 32) softmax_kernel(
    bf16* __restrict__ Sh, bf16* __restrict__ Sl, int n)
{
    const long long rb = ((long long)blockIdx.y * n + blockIdx.x) * n;
    const int tid = threadIdx.x;
    constexpr int NT = NW * 32;

    float2 v[CNT];
#pragma unroll
    for (int t = 0; t < CNT; t++) {
        const long long idx = rb + (long long)(tid + t * NT) * 2;
        unsigned uh = *reinterpret_cast<const unsigned*>(&Sh[idx]);
        unsigned ul = *reinterpret_cast<const unsigned*>(&Sl[idx]);
        __nv_bfloat162 bh = *reinterpret_cast<__nv_bfloat162*>(&uh);
        __nv_bfloat162 bl = *reinterpret_cast<__nv_bfloat162*>(&ul);
        v[t].x = __bfloat162float(bh.x) + __bfloat162float(bl.x);
        v[t].y = __bfloat162float(bh.y) + __bfloat162float(bl.y);
    }

    float m = -1e30f;
#pragma unroll
    for (int t = 0; t < CNT; t++) m = fmaxf(m, fmaxf(v[t].x, v[t].y));
    __shared__ float sh[NW];
#pragma unroll
    for (int o = 16; o; o >>= 1) m = fmaxf(m, __shfl_xor_sync(0xffffffffu, m, o));
    if ((tid & 31) == 0) sh[tid >> 5] = m;
    __syncthreads();
    float mm = sh[0];
#pragma unroll
    for (int w = 1; w < NW; w++) mm = fmaxf(mm, sh[w]);

    float s = 0.f;
#pragma unroll
    for (int t = 0; t < CNT; t++) {
        v[t].x = expf(v[t].x - mm);
        v[t].y = expf(v[t].y - mm);
        s += v[t].x + v[t].y;
    }
    __syncthreads();
#pragma unroll
    for (int o = 16; o; o >>= 1) s += __shfl_xor_sync(0xffffffffu, s, o);
    if ((tid & 31) == 0) sh[tid >> 5] = s;
    __syncthreads();
    float tot = 0.f;
#pragma unroll
    for (int w = 0; w < NW; w++) tot += sh[w];
    const float inv = 1.f / tot;

#pragma unroll
    for (int t = 0; t < CNT; t++) {
        const long long idx = rb + (long long)(tid + t * NT) * 2;
        union { bf16 b[2]; unsigned u; } ph, pl;
        split1(v[t].x * inv, ph.b[0], pl.b[0]);
        split1(v[t].y * inv, ph.b[1], pl.b[1]);
        *reinterpret_cast<unsigned*>(&Sh[idx]) = ph.u;
        *reinterpret_cast<unsigned*>(&Sl[idx]) = pl.u;
    }
}

// =====================================================================
// Host-side helpers
// =====================================================================
template <int MODE, bool SO>
static inline void launch_mma(const bf16* Ah, const bf16* Al,
                              const bf16* Bh, const bf16* Bl,
                              const float* bias, const float* res, const float* rm,
                              float* Y, bf16* Yh, bf16* Yl,
                              int M, int N, int K, int ldx, int ldw, int ldy,
                              long long sX = 0, long long sW = 0, long long sY = 0,
                              int batch = 1, float alpha = 1.f)
{
    dim3 grid((M + 127) / 128, (N + 127) / 128, batch);
    mma_gemm_kernel<MODE, SO><<<grid, 256, GEMM_SMEM_BYTES>>>(
        Ah, Al, Bh, Bl, bias, res, rm, Y, Yh, Yl,
        M, N, K, ldx, ldw, ldy, sX, sW, sY, alpha);
}

static inline void launch_split(const float* s, bf16* h, bf16* l, long long cnt)
{
    long long n4 = cnt / 4;
    int grid = (int)((n4 + 255) / 256);
    if (grid > 4096) grid = 4096;
    split_kernel<<<grid, 256>>>(s, h, l, n4);
}

// Cached scratch pointers
static float *s0a, *s0b, *s1a, *s1b, *s2, *hl, *h1, *h2p;
static bf16 *f2h, *f2l, *f1h, *f1l, *f0h, *f0l;
static bf16 *wembh, *wembl, *wsageh, *wsagel, *wqkvh, *wqkvl, *wouth, *woutl;
static bf16 *wf1h, *wf1l, *wf2h, *wf2l, *wclsh, *wclsl;
static bf16 *cch, *ccl, *h1h, *h1l, *h2h, *h2l, *qkvh, *qkvl;
static bf16 *sch, *scl, *vth, *vtl, *aoh, *aol, *fmh, *fml, *s0h, *s0l;
static bool g_ptrs_ready = false;

#define SYM(p, s) cudaGetSymbolAddress((void**)&(p), s)
#define SETSMEM(MODE, SO) \
    cudaFuncSetAttribute(mma_gemm_kernel<MODE, SO>, \
        cudaFuncAttributeMaxDynamicSharedMemorySize, GEMM_SMEM_BYTES)

static void resolve_ptrs()
{
    if (g_ptrs_ready) return;
    SYM(s0a, g_s0a); SYM(s0b, g_s0b); SYM(s1a, g_s1a); SYM(s1b, g_s1b);
    SYM(s2, g_s2); SYM(hl, g_hlocal); SYM(h1, g_h1); SYM(h2p, g_h2);
    SYM(f2h, g_f2h); SYM(f2l, g_f2l); SYM(f1h, g_f1h); SYM(f1l, g_f1l);
    SYM(f0h, g_f0h); SYM(f0l, g_f0l);
    SYM(wembh, g_wembh); SYM(wembl, g_wembl);
    SYM(wsageh, g_wsageh); SYM(wsagel, g_wsagel);
    SYM(wqkvh, g_wqkvh); SYM(wqkvl, g_wqkvl);
    SYM(wouth, g_wouth); SYM(woutl, g_woutl);
    SYM(wf1h, g_wf1h); SYM(wf1l, g_wf1l);
    SYM(wf2h, g_wf2h); SYM(wf2l, g_wf2l);
    SYM(wclsh, g_wclsh); SYM(wclsl, g_wclsl);
    SYM(cch, g_cch); SYM(ccl, g_ccl);
    SYM(h1h, g_h1h); SYM(h1l, g_h1l);
    SYM(h2h, g_h2h); SYM(h2l, g_h2l);
    SYM(qkvh, g_qkvh); SYM(qkvl, g_qkvl);
    SYM(sch, g_sch); SYM(scl, g_scl);
    SYM(vth, g_vth); SYM(vtl, g_vtl);
    SYM(aoh, g_aoh); SYM(aol, g_aol);
    SYM(fmh, g_fmh); SYM(fml, g_fml);
    SYM(s0h, g_s0h); SYM(s0l, g_s0l);
    SETSMEM(0, false); SETSMEM(0, true);
    SETSMEM(1, false);
    SETSMEM(2, true);
    SETSMEM(3, true);
    SETSMEM(4, false); SETSMEM(4, true);
    g_ptrs_ready = true;
}

extern "C" void kernel_launch(void* const* d_in, const int* in_sizes, int n_in,
                              void* d_out, int out_size)
{
    (void)in_sizes; (void)n_in; (void)out_size;
    const float* feats0  = (const float*)d_in[0];
    const float* feats1  = (const float*)d_in[1];
    const float* feats2  = (const float*)d_in[2];
    const float* nmask0  = (const float*)d_in[3];
    const float* nmask1  = (const float*)d_in[4];
    const float* nmask2  = (const float*)d_in[5];
    const int*   nbmask0 = (const int*)d_in[6];
    const int*   nbmask1 = (const int*)d_in[7];
    const float* emb_w   = (const float*)d_in[8];
    const float* emb_b   = (const float*)d_in[9];
    const float* sage_w  = (const float*)d_in[10];
    const float* sage_b  = (const float*)d_in[11];
    const float* qkv_w   = (const float*)d_in[12];
    const float* qkv_b   = (const float*)d_in[13];
    const float* out_w   = (const float*)d_in[14];
    const float* out_b   = (const float*)d_in[15];
    const float* n1_g    = (const float*)d_in[16];
    const float* n1_b    = (const float*)d_in[17];
    const float* n2_g    = (const float*)d_in[18];
    const float* n2_b    = (const float*)d_in[19];
    const float* ffn_w1  = (const float*)d_in[20];
    const float* ffn_b1  = (const float*)d_in[21];
    const float* ffn_w2  = (const float*)d_in[22];
    const float* ffn_b2  = (const float*)d_in[23];
    const float* cls_w   = (const float*)d_in[24];
    const float* cls_b   = (const float*)d_in[25];
    float* out = (float*)d_out;

    resolve_ptrs();

    // ---- pre-split inputs & weights (bf16 hi/lo) ----
    launch_split(feats2, f2h, f2l, (long long)N2 * INDIM);
    launch_split(feats1, f1h, f1l, (long long)N1 * INDIM);
    launch_split(feats0, f0h, f0l, (long long)N0 * INDIM);
    launch_split(emb_w,  wembh, wembl, (long long)CDIM * INDIM);
    launch_split(sage_w, wsageh, wsagel, (long long)NL * CDIM * 2 * CDIM);
    launch_split(qkv_w,  wqkvh, wqkvl, (long long)NL * 3 * CDIM * CDIM);
    launch_split(out_w,  wouth, woutl, (long long)NL * CDIM * CDIM);
    launch_split(ffn_w1, wf1h, wf1l, (long long)NL * 2 * CDIM * CDIM);
    launch_split(ffn_w2, wf2h, wf2l, (long long)NL * CDIM * 2 * CDIM);
    launch_split(cls_w,  wclsh, wclsl, (long long)NCLS * CDIM);

    // ---- embeddings ----
    launch_mma<1, false>(f2h, f2l, wembh, wembl, emb_b, nullptr, nmask2,
                         s2, nullptr, nullptr, N2, CDIM, INDIM, INDIM, INDIM, CDIM);
    launch_mma<1, false>(f1h, f1l, wembh, wembl, emb_b, nullptr, nmask1,
                         s1a, nullptr, nullptr, N1, CDIM, INDIM, INDIM, INDIM, CDIM);
    launch_mma<1, false>(f0h, f0l, wembh, wembl, emb_b, nullptr, nmask0,
                         s0a, nullptr, nullptr, N0, CDIM, INDIM, INDIM, INDIM, CDIM);

    struct Step { int li, n; float *sf, *child, *outb; const int* nbm; const float* nm; bool last; };
    Step steps[3] = {
        {0, N1, s1a, s2,  s1b, nbmask1, nmask1, false},
        {0, N0, s0a, s1a, s0b, nbmask0, nmask0, false},
        {1, N0, s0b, s1b, nullptr, nbmask0, nmask0, true},
    };

    const float scale = 1.f / sqrtf((float)DHEAD);

    for (int si = 0; si < 3; si++) {
        const Step& st = steps[si];
        const int li = st.li, n = st.n;
        const bf16* swh = wsageh + (long long)li * CDIM * 2 * CDIM;
        const bf16* swl = wsagel + (long long)li * CDIM * 2 * CDIM;
        const float* sb = sage_b + li * CDIM;
        const bf16* qwh = wqkvh + (long long)li * 3 * CDIM * CDIM;
        const bf16* qwl = wqkvl + (long long)li * 3 * CDIM * CDIM;
        const float* qb = qkv_b + li * 3 * CDIM;
        const bf16* owh = wouth + (long long)li * CDIM * CDIM;
        const bf16* owl = woutl + (long long)li * CDIM * CDIM;
        const float* ob = out_b + li * CDIM;
        const float* g1 = n1_g + li * CDIM, *b1 = n1_b + li * CDIM;
        const float* g2 = n2_g + li * CDIM, *b2 = n2_b + li * CDIM;
        const bf16* f1wh = wf1h + (long long)li * 2 * CDIM * CDIM;
        const bf16* f1wl = wf1l + (long long)li * 2 * CDIM * CDIM;
        const float* fb1 = ffn_b1 + li * 2 * CDIM;
        const bf16* f2wh = wf2h + (long long)li * CDIM * 2 * CDIM;
        const bf16* f2wl = wf2l + (long long)li * CDIM * 2 * CDIM;
        const float* fb2 = ffn_b2 + li * CDIM;

        // 1) aggregate + concat -> split cc
        agg_concat_kernel<<<n, 128>>>(cch, ccl, st.sf, st.child, st.nbm);
        // 2) h_local = cc @ sage_w^T + sage_b
        launch_mma<0, false>(cch, ccl, swh, swl, sb, nullptr, nullptr,
                             hl, nullptr, nullptr,
                             n, CDIM, 2 * CDIM, 2 * CDIM, 2 * CDIM, CDIM);
        // 3) h1 = LN(sf + h_local)
        ln_res_kernel<<<n, 128>>>(h1, h1h, h1l, st.sf, hl, g1, b1);
        // 4) qkv
        launch_mma<0, true>(h1h, h1l, qwh, qwl, qb, nullptr, nullptr,
                            nullptr, qkvh, qkvl,
                            n, 3 * CDIM, CDIM, CDIM, CDIM, 3 * CDIM);
        // 5) scores = scale * Q K^T  (batched heads; split-bf16 out)
        launch_mma<2, true>(qkvh, qkvl, qkvh + CDIM, qkvl + CDIM,
                            nullptr, nullptr, nullptr,
                            nullptr, sch, scl,
                            n, n, DHEAD, 3 * CDIM, 3 * CDIM, n,
                            DHEAD, DHEAD, (long long)n * n, NHEAD, scale);
        // 6) softmax in-place on split scores
        if (n == N1) softmax_kernel<8, 8><<<dim3(N1, NHEAD), 256>>>(sch, scl, n);
        else         softmax_kernel<1, 4><<<dim3(N0, NHEAD), 128>>>(sch, scl, n);
        // 6b) transpose V -> Vt[h][d][tok]
        transpose_v_kernel<<<dim3(n / 32, DHEAD / 32, NHEAD), dim3(32, 8)>>>(
            qkvh, qkvl, vth, vtl, n);
        // 7) O_h = P_h @ V_h^T
        launch_mma<2, true>(sch, scl, vth, vtl,
                            nullptr, nullptr, nullptr,
                            nullptr, aoh, aol,
                            n, DHEAD, n, n, n, CDIM,
                            (long long)n * n, (long long)DHEAD * n, DHEAD, NHEAD, 1.f);
        // 8) proj
        launch_mma<0, false>(aoh, aol, owh, owl, ob, nullptr, nullptr,
                             hl, nullptr, nullptr,
                             n, CDIM, CDIM, CDIM, CDIM, CDIM);
        // 9) h2 = LN(h1 + proj)
        ln_res_kernel<<<n, 128>>>(h2p, h2h, h2l, h1, hl, g2, b2);
        // 10) mid = relu(...)
        launch_mma<3, true>(h2h, h2l, f1wh, f1wl, fb1, nullptr, nullptr,
                            nullptr, fmh, fml,
                            n, 2 * CDIM, CDIM, CDIM, CDIM, 2 * CDIM);
        // 11) state
        if (st.last)
            launch_mma<4, true>(fmh, fml, f2wh, f2wl, fb2, h2p, st.nm,
                                nullptr, s0h, s0l,
                                n, CDIM, 2 * CDIM, 2 * CDIM, 2 * CDIM, CDIM);
        else
            launch_mma<4, false>(fmh, fml, f2wh, f2wl, fb2, h2p, st.nm,
                                 st.outb, nullptr, nullptr,
                                 n, CDIM, 2 * CDIM, 2 * CDIM, 2 * CDIM, CDIM);
    }

    // ---- classifier ----
    launch_mma<0, false>(s0h, s0l, wclsh, wclsl, cls_b, nullptr, nullptr,
                         out, nullptr, nullptr,
                         N0, NCLS, CDIM, CDIM, CDIM, NCLS);
}

// round 14
// speedup vs baseline: 1.0230x; 1.0016x over previous
#include <cuda_runtime.h>
#include <cuda_bf16.h>
#include <math.h>

// ---------------- problem dims ----------------
#define CDIM 512
#define INDIM 256
#define NHEAD 4
#define DHEAD 128
#define FANOUT 16
#define NCLS 47
#define N0 256
#define N1 4096
#define N2 65536
#define NL 2

typedef __nv_bfloat16 bf16;

// ---------------- fp32 scratch ----------------
__device__ float g_s0a[N0 * CDIM];
__device__ float g_s0b[N0 * CDIM];
__device__ float g_s1a[N1 * CDIM];
__device__ float g_s1b[N1 * CDIM];
__device__ float g_s2[(long long)N2 * CDIM];
__device__ float g_hlocal[N1 * CDIM];
__device__ float g_h1[N1 * CDIM];
__device__ float g_h2[N1 * CDIM];

// ---------------- split-bf16 scratch (hi/lo) ----------------
__device__ bf16 g_f2h[(long long)N2 * INDIM], g_f2l[(long long)N2 * INDIM];
__device__ bf16 g_f1h[N1 * INDIM], g_f1l[N1 * INDIM];
__device__ bf16 g_f0h[N0 * INDIM], g_f0l[N0 * INDIM];
__device__ bf16 g_wembh[CDIM * INDIM], g_wembl[CDIM * INDIM];
__device__ bf16 g_wsageh[NL * CDIM * 2 * CDIM], g_wsagel[NL * CDIM * 2 * CDIM];
__device__ bf16 g_wqkvh[NL * 3 * CDIM * CDIM], g_wqkvl[NL * 3 * CDIM * CDIM];
__device__ bf16 g_wouth[NL * CDIM * CDIM], g_woutl[NL * CDIM * CDIM];
__device__ bf16 g_wf1h[NL * 2 * CDIM * CDIM], g_wf1l[NL * 2 * CDIM * CDIM];
__device__ bf16 g_wf2h[NL * CDIM * 2 * CDIM], g_wf2l[NL * CDIM * 2 * CDIM];
__device__ bf16 g_wclsh[NCLS * CDIM + 64], g_wclsl[NCLS * CDIM + 64];
__device__ bf16 g_cch[N1 * 2 * CDIM], g_ccl[N1 * 2 * CDIM];
__device__ bf16 g_h1h[N1 * CDIM], g_h1l[N1 * CDIM];
__device__ bf16 g_h2h[N1 * CDIM], g_h2l[N1 * CDIM];
__device__ bf16 g_qkvh[N1 * 3 * CDIM], g_qkvl[N1 * 3 * CDIM];
__device__ bf16 g_sch[(long long)NHEAD * N1 * N1], g_scl[(long long)NHEAD * N1 * N1];
__device__ bf16 g_vth[NHEAD * DHEAD * N1], g_vtl[NHEAD * DHEAD * N1];
__device__ bf16 g_aoh[N1 * CDIM], g_aol[N1 * CDIM];
__device__ bf16 g_fmh[N1 * 2 * CDIM], g_fml[N1 * 2 * CDIM];
__device__ bf16 g_s0h[N0 * CDIM], g_s0l[N0 * CDIM];

// =====================================================================
// split helpers
// =====================================================================
__device__ __forceinline__ void split1(float x, bf16& h, bf16& l)
{
    h = __float2bfloat16(x);
    l = __float2bfloat16(x - __bfloat162float(h));
}

__global__ void split_kernel(const float* __restrict__ src,
                             bf16* __restrict__ h, bf16* __restrict__ l, long long n4)
{
    for (long long i = blockIdx.x * (long long)blockDim.x + threadIdx.x;
         i < n4; i += (long long)gridDim.x * blockDim.x) {
        float4 v = reinterpret_cast<const float4*>(src)[i];
        union { bf16 b[4]; uint2 u; } uh, ul;
        split1(v.x, uh.b[0], ul.b[0]);
        split1(v.y, uh.b[1], ul.b[1]);
        split1(v.z, uh.b[2], ul.b[2]);
        split1(v.w, uh.b[3], ul.b[3]);
        reinterpret_cast<uint2*>(h)[i] = uh.u;
        reinterpret_cast<uint2*>(l)[i] = ul.u;
    }
}

// =====================================================================
// Tensor-core GEMM (mma.sync bf16, 3-pass split), TRANSB layout:
//   Y = op( A[M,K] * B[N,K]^T )
// Block 128x128x32, 256 thr, 8 warps (4m x 2n), warp tile 32x64.
// 2-stage cp.async (80 KB smem -> 2 CTAs/SM); fragments via ldmatrix.x4.
// MODE: 0 +bias | 1 (+bias)*rowmask | 2 *alpha | 3 relu(+bias)
//       4 (res + v + bias)*rowmask
// SPLIT_OUT: write (Yh, Yl) bf16 instead of fp32 Y.
// =====================================================================
__device__ __forceinline__ void mma16816(float* c, const unsigned* a, const unsigned* b)
{
    asm volatile(
        "mma.sync.aligned.m16n8k16.row.col.f32.bf16.bf16.f32 "
        "{%0,%1,%2,%3}, {%4,%5,%6,%7}, {%8,%9}, {%0,%1,%2,%3};\n"
        : "+f"(c[0]), "+f"(c[1]), "+f"(c[2]), "+f"(c[3])
        : "r"(a[0]), "r"(a[1]), "r"(a[2]), "r"(a[3]), "r"(b[0]), "r"(b[1]));
}

__device__ __forceinline__ void ldsm4(unsigned* d, unsigned saddr)
{
    asm volatile(
        "ldmatrix.sync.aligned.m8n8.x4.shared.b16 {%0,%1,%2,%3}, [%4];\n"
        : "=r"(d[0]), "=r"(d[1]), "=r"(d[2]), "=r"(d[3]) : "r"(saddr));
}

__device__ __forceinline__ void cp16(unsigned s, const void* g, bool v)
{
    asm volatile("cp.async.cg.shared.global [%0], [%1], 16, %2;\n"
                 :: "r"(s), "l"(g), "r"(v ? 16 : 0));
}
__device__ __forceinline__ void cp_commit()
{
    asm volatile("cp.async.commit_group;\n" ::);
}

#define GEMM_SMEM_BYTES (2 * 4 * 128 * 40 * 2)   // 81920 -> 2 CTAs/SM

template <int MODE, bool SPLIT_OUT>
__global__ void __launch_bounds__(256) mma_gemm_kernel(
    const bf16* __restrict__ Ahg, const bf16* __restrict__ Alg,
    const bf16* __restrict__ Bhg, const bf16* __restrict__ Blg,
    const float* __restrict__ bias, const float* __restrict__ res,
    const float* __restrict__ rowmask,
    float* __restrict__ Yg, bf16* __restrict__ Yhg, bf16* __restrict__ Ylg,
    int M, int N, int K, int ldx, int ldw, int ldy,
    long long sX, long long sW, long long sY, float alpha)
{
    constexpr int BM = 128, BN = 128, BK = 32;
    constexpr int LDA = 40;                 // pitch (elems); 80B rows, LDSM-clean
    constexpr int SZ  = BM * LDA;           // elems per stage per tensor

    extern __shared__ __align__(16) char smem_raw[];
    const unsigned sbase = (unsigned)__cvta_generic_to_shared(smem_raw);
    const unsigned offAh = 0;
    const unsigned offAl = 2 * SZ * 2;
    const unsigned offBh = 4 * SZ * 2;
    const unsigned offBl = 6 * SZ * 2;

    const bf16* Ah = Ahg + (long long)blockIdx.z * sX;
    const bf16* Al = Alg + (long long)blockIdx.z * sX;
    const bf16* Bh = Bhg + (long long)blockIdx.z * sW;
    const bf16* Bl = Blg + (long long)blockIdx.z * sW;
    float* Y  = Yg  ? Yg  + (long long)blockIdx.z * sY : nullptr;
    bf16*  Yh = Yhg ? Yhg + (long long)blockIdx.z * sY : nullptr;
    bf16*  Yl = Ylg ? Ylg + (long long)blockIdx.z * sY : nullptr;

    const int tid  = threadIdx.x;
    const int warp = tid >> 5;
    const int lane = tid & 31;
    const int wm   = warp & 3;          // 4 m-tiles of 32
    const int wn   = warp >> 2;         // 2 n-tiles of 64
    const int m0   = blockIdx.x * BM;
    const int n0   = blockIdx.y * BN;
    const int r    = lane >> 2;
    const int c2   = (lane & 3) * 2;

    // LDSM per-lane address pieces: lanes 0-15 -> rows, lanes 16-31 -> k+8
    const int lane15 = lane & 15;
    const int khalf  = (lane >> 4) << 3;          // 0 or 8
    const int aFrag  = (wm * 32 + lane15) * LDA + khalf;   // + mt*16*LDA + koff
    const int bFrag  = (wn * 64 + lane15) * LDA + khalf;   // + j*16*LDA + koff

    const int lrow = tid >> 2;          // cp.async: 0..63 (+64 second pass)
    const int lq   = (tid & 3) * 8;

    float acc[2][8][4];
#pragma unroll
    for (int mt = 0; mt < 2; mt++)
#pragma unroll
        for (int nt = 0; nt < 8; nt++)
#pragma unroll
            for (int e = 0; e < 4; e++) acc[mt][nt][e] = 0.f;

    const int nk = K / BK;

    auto cp_stage = [&](int buf, int kt) {
        const int k0 = kt * BK;
#pragma unroll
        for (int it = 0; it < 2; it++) {
            const int row = lrow + it * 64;
            const unsigned soff = (unsigned)((buf * SZ + row * LDA + lq) * 2);
            const bool va = (m0 + row) < M;
            const long long ga = (long long)(m0 + row) * ldx + k0 + lq;
            cp16(sbase + offAh + soff, va ? (const void*)(Ah + ga) : (const void*)Ah, va);
            cp16(sbase + offAl + soff, va ? (const void*)(Al + ga) : (const void*)Al, va);
            const bool vb = (n0 + row) < N;
            const long long gb = (long long)(n0 + row) * ldw + k0 + lq;
            cp16(sbase + offBh + soff, vb ? (const void*)(Bh + gb) : (const void*)Bh, vb);
            cp16(sbase + offBl + soff, vb ? (const void*)(Bl + gb) : (const void*)Bl, vb);
        }
        cp_commit();
    };

    cp_stage(0, 0);

    for (int t = 0; t < nk; t++) {
        const int buf = t & 1;
        if (t + 1 < nk) {
            cp_stage(buf ^ 1, t + 1);
            asm volatile("cp.async.wait_group 1;\n" ::);
        } else {
            asm volatile("cp.async.wait_group 0;\n" ::);
        }
        __syncthreads();

        const unsigned sb2 = (unsigned)(buf * SZ * 2);

#pragma unroll
        for (int ks = 0; ks < 2; ks++) {
            const int koff = ks * 16;
            unsigned ah[2][4], al[2][4], bh[8][2], bl[8][2];
#pragma unroll
            for (int mt = 0; mt < 2; mt++) {
                const unsigned ao = sb2 + (unsigned)((aFrag + mt * 16 * LDA + koff) * 2);
                ldsm4(ah[mt], sbase + offAh + ao);
                ldsm4(al[mt], sbase + offAl + ao);
            }
#pragma unroll
            for (int j = 0; j < 4; j++) {
                const unsigned bo = sb2 + (unsigned)((bFrag + j * 16 * LDA + koff) * 2);
                unsigned d[4];
                ldsm4(d, sbase + offBh + bo);
                bh[2 * j][0] = d[0]; bh[2 * j + 1][0] = d[1];
                bh[2 * j][1] = d[2]; bh[2 * j + 1][1] = d[3];
                ldsm4(d, sbase + offBl + bo);
                bl[2 * j][0] = d[0]; bl[2 * j + 1][0] = d[1];
                bl[2 * j][1] = d[2]; bl[2 * j + 1][1] = d[3];
            }
#pragma unroll
            for (int mt = 0; mt < 2; mt++)
#pragma unroll
                for (int nt = 0; nt < 8; nt++) {
                    mma16816(acc[mt][nt], ah[mt], bh[nt]);
                    mma16816(acc[mt][nt], ah[mt], bl[nt]);
                    mma16816(acc[mt][nt], al[mt], bh[nt]);
                }
        }
        __syncthreads();
    }

    // ---- epilogue ----
#pragma unroll
    for (int mt = 0; mt < 2; mt++) {
#pragma unroll
        for (int nt = 0; nt < 8; nt++) {
#pragma unroll
            for (int e = 0; e < 4; e++) {
                const int gr = m0 + wm * 32 + mt * 16 + r + (e >= 2 ? 8 : 0);
                const int gc = n0 + wn * 64 + nt * 8 + c2 + (e & 1);
                if (gr >= M || gc >= N) continue;
                float v = acc[mt][nt][e];
                if (MODE == 0)      v = v + bias[gc];
                else if (MODE == 1) v = (v + bias[gc]) * rowmask[gr];
                else if (MODE == 2) v = v * alpha;
                else if (MODE == 3) v = fmaxf(v + bias[gc], 0.f);
                else if (MODE == 4) v = (res[(long long)gr * ldy + gc] + v + bias[gc]) * rowmask[gr];
                const long long off = (long long)gr * ldy + gc;
                if (SPLIT_OUT) {
                    bf16 h, l; split1(v, h, l);
                    Yh[off] = h; Yl[off] = l;
                } else {
                    Y[off] = v;
                }
            }
        }
    }
}

// =====================================================================
// V transpose: qkv[tok][2C + h*DH + d] -> Vt[h][d][tok]  (split bf16)
// =====================================================================
__global__ void __launch_bounds__(256) transpose_v_kernel(
    const bf16* __restrict__ qh, const bf16* __restrict__ ql,
    bf16* __restrict__ vh, bf16* __restrict__ vl, int n)
{
    __shared__ bf16 th[32][34], tl[32][34];
    const int hh = blockIdx.z;
    const int tok0 = blockIdx.x * 32, d0 = blockIdx.y * 32;
    const int tx = threadIdx.x, ty = threadIdx.y;
#pragma unroll
    for (int rr = ty; rr < 32; rr += 8) {
        const long long src = (long long)(tok0 + rr) * (3 * CDIM) + 2 * CDIM + hh * DHEAD + d0 + tx;
        th[rr][tx] = qh[src];
        tl[rr][tx] = ql[src];
    }
    __syncthreads();
#pragma unroll
    for (int rr = ty; rr < 32; rr += 8) {
        const long long dst = ((long long)hh * DHEAD + d0 + rr) * n + tok0 + tx;
        vh[dst] = th[tx][rr];
        vl[dst] = tl[tx][rr];
    }
}

// =====================================================================
// Masked-mean aggregation + concat -> split-bf16 cc
// =====================================================================
__global__ void __launch_bounds__(128) agg_concat_kernel(
    bf16* __restrict__ outh, bf16* __restrict__ outl,
    const float* __restrict__ sf, const float* __restrict__ child,
    const int* __restrict__ nbm)
{
    const int i = blockIdx.x;
    const int tid = threadIdx.x;
    __shared__ float mk[FANOUT];
    __shared__ float invd;
    if (tid < FANOUT) mk[tid] = (float)nbm[i * FANOUT + tid];
    __syncthreads();
    if (tid == 0) {
        float s = 0.f;
#pragma unroll
        for (int f = 0; f < FANOUT; f++) s += mk[f];
        invd = 1.f / fmaxf(s, 1.f);
    }
    __syncthreads();
    const float dinv = invd;
    const long long ob = (long long)i * (2 * CDIM) + tid * 4;

    float4 v0 = *reinterpret_cast<const float4*>(sf + (long long)i * CDIM + tid * 4);
    union { bf16 b[4]; uint2 u; } uh, ul;
    split1(v0.x, uh.b[0], ul.b[0]); split1(v0.y, uh.b[1], ul.b[1]);
    split1(v0.z, uh.b[2], ul.b[2]); split1(v0.w, uh.b[3], ul.b[3]);
    *reinterpret_cast<uint2*>(outh + ob) = uh.u;
    *reinterpret_cast<uint2*>(outl + ob) = ul.u;

    float4 acc = make_float4(0.f, 0.f, 0.f, 0.f);
    const float* cb = child + (long long)i * FANOUT * CDIM + tid * 4;
#pragma unroll
    for (int f = 0; f < FANOUT; f++) {
        float4 v = *reinterpret_cast<const float4*>(cb + f * CDIM);
        float w = mk[f];
        acc.x += v.x * w; acc.y += v.y * w; acc.z += v.z * w; acc.w += v.w * w;
    }
    acc.x *= dinv; acc.y *= dinv; acc.z *= dinv; acc.w *= dinv;
    split1(acc.x, uh.b[0], ul.b[0]); split1(acc.y, uh.b[1], ul.b[1]);
    split1(acc.z, uh.b[2], ul.b[2]); split1(acc.w, uh.b[3], ul.b[3]);
    *reinterpret_cast<uint2*>(outh + ob + CDIM) = uh.u;
    *reinterpret_cast<uint2*>(outl + ob + CDIM) = ul.u;
}

// =====================================================================
// Residual + LayerNorm: fp32 out + fused split-bf16 out
// =====================================================================
__global__ void __launch_bounds__(128) ln_res_kernel(
    float* __restrict__ out, bf16* __restrict__ outh, bf16* __restrict__ outl,
    const float* __restrict__ a, const float* __restrict__ b,
    const float* __restrict__ g, const float* __restrict__ be)
{
    const long long base = (long long)blockIdx.x * CDIM;
    const int tid = threadIdx.x;
    float4 va = *reinterpret_cast<const float4*>(a + base + tid * 4);
    float4 vb = *reinterpret_cast<const float4*>(b + base + tid * 4);
    float x0 = va.x + vb.x, x1 = va.y + vb.y, x2 = va.z + vb.z, x3 = va.w + vb.w;
    float s = x0 + x1 + x2 + x3;
    float q = x0 * x0 + x1 * x1 + x2 * x2 + x3 * x3;
#pragma unroll
    for (int o = 16; o; o >>= 1) {
        s += __shfl_xor_sync(0xffffffffu, s, o);
        q += __shfl_xor_sync(0xffffffffu, q, o);
    }
    __shared__ float shs[4], shq[4];
    if ((tid & 31) == 0) { shs[tid >> 5] = s; shq[tid >> 5] = q; }
    __syncthreads();
    s = shs[0] + shs[1] + shs[2] + shs[3];
    q = shq[0] + shq[1] + shq[2] + shq[3];
    const float mu  = s * (1.f / CDIM);
    const float var = q * (1.f / CDIM) - mu * mu;
    const float rr  = rsqrtf(var + 1e-5f);
    float4 vg  = *reinterpret_cast<const float4*>(g + tid * 4);
    float4 vbe = *reinterpret_cast<const float4*>(be + tid * 4);
    float4 o4;
    o4.x = (x0 - mu) * rr * vg.x + vbe.x;
    o4.y = (x1 - mu) * rr * vg.y + vbe.y;
    o4.z = (x2 - mu) * rr * vg.z + vbe.z;
    o4.w = (x3 - mu) * rr * vg.w + vbe.w;
    *reinterpret_cast<float4*>(out + base + tid * 4) = o4;
    union { bf16 bb[4]; uint2 u; } uh, ul;
    split1(o4.x, uh.bb[0], ul.bb[0]); split1(o4.y, uh.bb[1], ul.bb[1]);
    split1(o4.z, uh.bb[2], ul.bb[2]); split1(o4.w, uh.bb[3], ul.bb[3]);
    *reinterpret_cast<uint2*>(outh + base + tid * 4) = uh.u;
    *reinterpret_cast<uint2*>(outl + base + tid * 4) = ul.u;
}

// =====================================================================
// In-place row softmax on split-bf16 scores (hi+lo reconstructed).
// =====================================================================
template <int CNT, int NW>
__global__ void __launch_bounds__(NW * 32) softmax_kernel(
    bf16* __restrict__ Sh, bf16* __restrict__ Sl, int n)
{
    const long long rb = ((long long)blockIdx.y * n + blockIdx.x) * n;
    const int tid = threadIdx.x;
    constexpr int NT = NW * 32;

    float2 v[CNT];
#pragma unroll
    for (int t = 0; t < CNT; t++) {
        const long long idx = rb + (long long)(tid + t * NT) * 2;
        unsigned uh = *reinterpret_cast<const unsigned*>(&Sh[idx]);
        unsigned ul = *reinterpret_cast<const unsigned*>(&Sl[idx]);
        __nv_bfloat162 bh = *reinterpret_cast<__nv_bfloat162*>(&uh);
        __nv_bfloat162 bl = *reinterpret_cast<__nv_bfloat162*>(&ul);
        v[t].x = __bfloat162float(bh.x) + __bfloat162float(bl.x);
        v[t].y = __bfloat162float(bh.y) + __bfloat162float(bl.y);
    }

    float m = -1e30f;
#pragma unroll
    for (int t = 0; t < CNT; t++) m = fmaxf(m, fmaxf(v[t].x, v[t].y));
    __shared__ float sh[NW];
#pragma unroll
    for (int o = 16; o; o >>= 1) m = fmaxf(m, __shfl_xor_sync(0xffffffffu, m, o));
    if ((tid & 31) == 0) sh[tid >> 5] = m;
    __syncthreads();
    float mm = sh[0];
#pragma unroll
    for (int w = 1; w < NW; w++) mm = fmaxf(mm, sh[w]);

    float s = 0.f;
#pragma unroll
    for (int t = 0; t < CNT; t++) {
        v[t].x = expf(v[t].x - mm);
        v[t].y = expf(v[t].y - mm);
        s += v[t].x + v[t].y;
    }
    __syncthreads();
#pragma unroll
    for (int o = 16; o; o >>= 1) s += __shfl_xor_sync(0xffffffffu, s, o);
    if ((tid & 31) == 0) sh[tid >> 5] = s;
    __syncthreads();
    float tot = 0.f;
#pragma unroll
    for (int w = 0; w < NW; w++) tot += sh[w];
    const float inv = 1.f / tot;

#pragma unroll
    for (int t = 0; t < CNT; t++) {
        const long long idx = rb + (long long)(tid + t * NT) * 2;
        union { bf16 b[2]; unsigned u; } ph, pl;
        split1(v[t].x * inv, ph.b[0], pl.b[0]);
        split1(v[t].y * inv, ph.b[1], pl.b[1]);
        *reinterpret_cast<unsigned*>(&Sh[idx]) = ph.u;
        *reinterpret_cast<unsigned*>(&Sl[idx]) = pl.u;
    }
}

// =====================================================================
// Host-side helpers
// =====================================================================
template <int MODE, bool SO>
static inline void launch_mma(const bf16* Ah, const bf16* Al,
                              const bf16* Bh, const bf16* Bl,
                              const float* bias, const float* res, const float* rm,
                              float* Y, bf16* Yh, bf16* Yl,
                              int M, int N, int K, int ldx, int ldw, int ldy,
                              long long sX = 0, long long sW = 0, long long sY = 0,
                              int batch = 1, float alpha = 1.f)
{
    dim3 grid((M + 127) / 128, (N + 127) / 128, batch);
    mma_gemm_kernel<MODE, SO><<<grid, 256, GEMM_SMEM_BYTES>>>(
        Ah, Al, Bh, Bl, bias, res, rm, Y, Yh, Yl,
        M, N, K, ldx, ldw, ldy, sX, sW, sY, alpha);
}

static inline void launch_split(const float* s, bf16* h, bf16* l, long long cnt)
{
    long long n4 = cnt / 4;
    int grid = (int)((n4 + 255) / 256);
    if (grid > 4096) grid = 4096;
    split_kernel<<<grid, 256>>>(s, h, l, n4);
}

// Cached scratch pointers
static float *s0a, *s0b, *s1a, *s1b, *s2, *hl, *h1, *h2p;
static bf16 *f2h, *f2l, *f1h, *f1l, *f0h, *f0l;
static bf16 *wembh, *wembl, *wsageh, *wsagel, *wqkvh, *wqkvl, *wouth, *woutl;
static bf16 *wf1h, *wf1l, *wf2h, *wf2l, *wclsh, *wclsl;
static bf16 *cch, *ccl, *h1h, *h1l, *h2h, *h2l, *qkvh, *qkvl;
static bf16 *sch, *scl, *vth, *vtl, *aoh, *aol, *fmh, *fml, *s0h, *s0l;
static bool g_ptrs_ready = false;

#define SYM(p, s) cudaGetSymbolAddress((void**)&(p), s)
#define SETSMEM(MODE, SO) \
    cudaFuncSetAttribute(mma_gemm_kernel<MODE, SO>, \
        cudaFuncAttributeMaxDynamicSharedMemorySize, GEMM_SMEM_BYTES)

static void resolve_ptrs()
{
    if (g_ptrs_ready) return;
    SYM(s0a, g_s0a); SYM(s0b, g_s0b); SYM(s1a, g_s1a); SYM(s1b, g_s1b);
    SYM(s2, g_s2); SYM(hl, g_hlocal); SYM(h1, g_h1); SYM(h2p, g_h2);
    SYM(f2h, g_f2h); SYM(f2l, g_f2l); SYM(f1h, g_f1h); SYM(f1l, g_f1l);
    SYM(f0h, g_f0h); SYM(f0l, g_f0l);
    SYM(wembh, g_wembh); SYM(wembl, g_wembl);
    SYM(wsageh, g_wsageh); SYM(wsagel, g_wsagel);
    SYM(wqkvh, g_wqkvh); SYM(wqkvl, g_wqkvl);
    SYM(wouth, g_wouth); SYM(woutl, g_woutl);
    SYM(wf1h, g_wf1h); SYM(wf1l, g_wf1l);
    SYM(wf2h, g_wf2h); SYM(wf2l, g_wf2l);
    SYM(wclsh, g_wclsh); SYM(wclsl, g_wclsl);
    SYM(cch, g_cch); SYM(ccl, g_ccl);
    SYM(h1h, g_h1h); SYM(h1l, g_h1l);
    SYM(h2h, g_h2h); SYM(h2l, g_h2l);
    SYM(qkvh, g_qkvh); SYM(qkvl, g_qkvl);
    SYM(sch, g_sch); SYM(scl, g_scl);
    SYM(vth, g_vth); SYM(vtl, g_vtl);
    SYM(aoh, g_aoh); SYM(aol, g_aol);
    SYM(fmh, g_fmh); SYM(fml, g_fml);
    SYM(s0h, g_s0h); SYM(s0l, g_s0l);
    SETSMEM(0, false); SETSMEM(0, true);
    SETSMEM(1, false);
    SETSMEM(2, true);
    SETSMEM(3, true);
    SETSMEM(4, false); SETSMEM(4, true);
    g_ptrs_ready = true;
}

extern "C" void kernel_launch(void* const* d_in, const int* in_sizes, int n_in,
                              void* d_out, int out_size)
{
    (void)in_sizes; (void)n_in; (void)out_size;
    const float* feats0  = (const float*)d_in[0];
    const float* feats1  = (const float*)d_in[1];
    const float* feats2  = (const float*)d_in[2];
    const float* nmask0  = (const float*)d_in[3];
    const float* nmask1  = (const float*)d_in[4];
    const float* nmask2  = (const float*)d_in[5];
    const int*   nbmask0 = (const int*)d_in[6];
    const int*   nbmask1 = (const int*)d_in[7];
    const float* emb_w   = (const float*)d_in[8];
    const float* emb_b   = (const float*)d_in[9];
    const float* sage_w  = (const float*)d_in[10];
    const float* sage_b  = (const float*)d_in[11];
    const float* qkv_w   = (const float*)d_in[12];
    const float* qkv_b   = (const float*)d_in[13];
    const float* out_w   = (const float*)d_in[14];
    const float* out_b   = (const float*)d_in[15];
    const float* n1_g    = (const float*)d_in[16];
    const float* n1_b    = (const float*)d_in[17];
    const float* n2_g    = (const float*)d_in[18];
    const float* n2_b    = (const float*)d_in[19];
    const float* ffn_w1  = (const float*)d_in[20];
    const float* ffn_b1  = (const float*)d_in[21];
    const float* ffn_w2  = (const float*)d_in[22];
    const float* ffn_b2  = (const float*)d_in[23];
    const float* cls_w   = (const float*)d_in[24];
    const float* cls_b   = (const float*)d_in[25];
    float* out = (float*)d_out;

    resolve_ptrs();

    // ---- pre-split inputs & weights (bf16 hi/lo) ----
    launch_split(feats2, f2h, f2l, (long long)N2 * INDIM);
    launch_split(feats1, f1h, f1l, (long long)N1 * INDIM);
    launch_split(feats0, f0h, f0l, (long long)N0 * INDIM);
    launch_split(emb_w,  wembh, wembl, (long long)CDIM * INDIM);
    launch_split(sage_w, wsageh, wsagel, (long long)NL * CDIM * 2 * CDIM);
    launch_split(qkv_w,  wqkvh, wqkvl, (long long)NL * 3 * CDIM * CDIM);
    launch_split(out_w,  wouth, woutl, (long long)NL * CDIM * CDIM);
    launch_split(ffn_w1, wf1h, wf1l, (long long)NL * 2 * CDIM * CDIM);
    launch_split(ffn_w2, wf2h, wf2l, (long long)NL * CDIM * 2 * CDIM);
    launch_split(cls_w,  wclsh, wclsl, (long long)NCLS * CDIM);

    // ---- embeddings ----
    launch_mma<1, false>(f2h, f2l, wembh, wembl, emb_b, nullptr, nmask2,
                         s2, nullptr, nullptr, N2, CDIM, INDIM, INDIM, INDIM, CDIM);
    launch_mma<1, false>(f1h, f1l, wembh, wembl, emb_b, nullptr, nmask1,
                         s1a, nullptr, nullptr, N1, CDIM, INDIM, INDIM, INDIM, CDIM);
    launch_mma<1, false>(f0h, f0l, wembh, wembl, emb_b, nullptr, nmask0,
                         s0a, nullptr, nullptr, N0, CDIM, INDIM, INDIM, INDIM, CDIM);

    struct Step { int li, n; float *sf, *child, *outb; const int* nbm; const float* nm; bool last; };
    Step steps[3] = {
        {0, N1, s1a, s2,  s1b, nbmask1, nmask1, false},
        {0, N0, s0a, s1a, s0b, nbmask0, nmask0, false},
        {1, N0, s0b, s1b, nullptr, nbmask0, nmask0, true},
    };

    const float scale = 1.f / sqrtf((float)DHEAD);

    for (int si = 0; si < 3; si++) {
        const Step& st = steps[si];
        const int li = st.li, n = st.n;
        const bf16* swh = wsageh + (long long)li * CDIM * 2 * CDIM;
        const bf16* swl = wsagel + (long long)li * CDIM * 2 * CDIM;
        const float* sb = sage_b + li * CDIM;
        const bf16* qwh = wqkvh + (long long)li * 3 * CDIM * CDIM;
        const bf16* qwl = wqkvl + (long long)li * 3 * CDIM * CDIM;
        const float* qb = qkv_b + li * 3 * CDIM;
        const bf16* owh = wouth + (long long)li * CDIM * CDIM;
        const bf16* owl = woutl + (long long)li * CDIM * CDIM;
        const float* ob = out_b + li * CDIM;
        const float* g1 = n1_g + li * CDIM, *b1 = n1_b + li * CDIM;
        const float* g2 = n2_g + li * CDIM, *b2 = n2_b + li * CDIM;
        const bf16* f1wh = wf1h + (long long)li * 2 * CDIM * CDIM;
        const bf16* f1wl = wf1l + (long long)li * 2 * CDIM * CDIM;
        const float* fb1 = ffn_b1 + li * 2 * CDIM;
        const bf16* f2wh = wf2h + (long long)li * CDIM * 2 * CDIM;
        const bf16* f2wl = wf2l + (long long)li * CDIM * 2 * CDIM;
        const float* fb2 = ffn_b2 + li * CDIM;

        // 1) aggregate + concat -> split cc
        agg_concat_kernel<<<n, 128>>>(cch, ccl, st.sf, st.child, st.nbm);
        // 2) h_local = cc @ sage_w^T + sage_b
        launch_mma<0, false>(cch, ccl, swh, swl, sb, nullptr, nullptr,
                             hl, nullptr, nullptr,
                             n, CDIM, 2 * CDIM, 2 * CDIM, 2 * CDIM, CDIM);
        // 3) h1 = LN(sf + h_local)
        ln_res_kernel<<<n, 128>>>(h1, h1h, h1l, st.sf, hl, g1, b1);
        // 4) qkv
        launch_mma<0, true>(h1h, h1l, qwh, qwl, qb, nullptr, nullptr,
                            nullptr, qkvh, qkvl,
                            n, 3 * CDIM, CDIM, CDIM, CDIM, 3 * CDIM);
        // 5) scores = scale * Q K^T  (batched heads; split-bf16 out)
        launch_mma<2, true>(qkvh, qkvl, qkvh + CDIM, qkvl + CDIM,
                            nullptr, nullptr, nullptr,
                            nullptr, sch, scl,
                            n, n, DHEAD, 3 * CDIM, 3 * CDIM, n,
                            DHEAD, DHEAD, (long long)n * n, NHEAD, scale);
        // 6) softmax in-place on split scores
        if (n == N1) softmax_kernel<8, 8><<<dim3(N1, NHEAD), 256>>>(sch, scl, n);
        else         softmax_kernel<1, 4><<<dim3(N0, NHEAD), 128>>>(sch, scl, n);
        // 6b) transpose V -> Vt[h][d][tok]
        transpose_v_kernel<<<dim3(n / 32, DHEAD / 32, NHEAD), dim3(32, 8)>>>(
            qkvh, qkvl, vth, vtl, n);
        // 7) O_h = P_h @ V_h^T
        launch_mma<2, true>(sch, scl, vth, vtl,
                            nullptr, nullptr, nullptr,
                            nullptr, aoh, aol,
                            n, DHEAD, n, n, n, CDIM,
                            (long long)n * n, (long long)DHEAD * n, DHEAD, NHEAD, 1.f);
        // 8) proj
        launch_mma<0, false>(aoh, aol, owh, owl, ob, nullptr, nullptr,
                             hl, nullptr, nullptr,
                             n, CDIM, CDIM, CDIM, CDIM, CDIM);
        // 9) h2 = LN(h1 + proj)
        ln_res_kernel<<<n, 128>>>(h2p, h2h, h2l, h1, hl, g2, b2);
        // 10) mid = relu(...)
        launch_mma<3, true>(h2h, h2l, f1wh, f1wl, fb1, nullptr, nullptr,
                            nullptr, fmh, fml,
                            n, 2 * CDIM, CDIM, CDIM, CDIM, 2 * CDIM);
        // 11) state
        if (st.last)
            launch_mma<4, true>(fmh, fml, f2wh, f2wl, fb2, h2p, st.nm,
                                nullptr, s0h, s0l,
                                n, CDIM, 2 * CDIM, 2 * CDIM, 2 * CDIM, CDIM);
        else
            launch_mma<4, false>(fmh, fml, f2wh, f2wl, fb2, h2p, st.nm,
                                 st.outb, nullptr, nullptr,
                                 n, CDIM, 2 * CDIM, 2 * CDIM, 2 * CDIM, CDIM);
    }

    // ---- classifier ----
    launch_mma<0, false>(s0h, s0l, wclsh, wclsl, cls_b, nullptr, nullptr,
                         out, nullptr, nullptr,
                         N0, NCLS, CDIM, CDIM, CDIM, NCLS);
}